// round 12
// baseline (speedup 1.0000x reference)
#include <cuda_runtime.h>
#include <cuda_fp16.h>
#include <math_constants.h>
#include <cstdint>
#include <cstddef>

#define N_USERS 10000
#define N_NEWS  10000
#define N_ENT   100000
#define N_RELS  32
#define DIM     64
#define KNB     20
#define NNZ_CNT 500000
#define LOG2E_F 1.44269504088896340736f

// -------------------- attention (mma.sync fp16) config ---------------------
#define QTILE   128
#define KTILE   64
#define QTILES  79                  // ceil(10000/128)
#define NKT     157                 // ceil(10000/64)
#define KVROWS  (NKT * KTILE)       // 10048 (48 zero-pad rows)
#define KSPL    15
#define ATT_UNITS (QTILES * KSPL)   // 1185

// fused grid: 1185 attn blocks interleaved 1:5 with 6250 entity blocks
#define ENT_BLOCKS ((N_ENT + 15) / 16)         // 6250
#define FUSE_BLOCKS (ATT_UNITS + ENT_BLOCKS)   // 7435
#define INTERLEAVE 6                           // 1185*6 = 7110 <= 7435

__device__ float g_po[(size_t)ATT_UNITS * 128 * 64];
__device__ float g_pl[(size_t)ATT_UNITS * 128];
__device__ float g_pm[(size_t)ATT_UNITS * 128];

__device__ __half g_kvhi[(size_t)KVROWS * DIM];
__device__ __half g_kvlo[(size_t)KVROWS * DIM];

// CSR scratch
__device__ int  g_cnt[N_USERS];
__device__ int  g_off[N_USERS + 1];
__device__ int2 g_pcv[NNZ_CNT];

// smem map (bytes): Q hi/lo 16KB each; 3 K buffers of (hi 8KB + lo 8KB)
#define SQHI  0
#define SQLO  16384
#define SKB(b)   (32768 + (b) * 16384)
#define SMEM_ATT 81920

// ----------------------------- helpers -------------------------------------
__device__ __forceinline__ uint32_t smem_u32(const void* p) {
    uint32_t a;
    asm("{ .reg .u64 t; cvta.to.shared.u64 t, %1; cvt.u32.u64 %0, t; }"
        : "=r"(a) : "l"(p));
    return a;
}
__device__ __forceinline__ void ldsm4(uint32_t r[4], uint32_t addr) {
    asm volatile("ldmatrix.sync.aligned.m8n8.x4.shared.b16 {%0,%1,%2,%3}, [%4];"
        : "=r"(r[0]), "=r"(r[1]), "=r"(r[2]), "=r"(r[3]) : "r"(addr));
}
__device__ __forceinline__ void ldsm4t(uint32_t r[4], uint32_t addr) {
    asm volatile("ldmatrix.sync.aligned.m8n8.x4.trans.shared.b16 {%0,%1,%2,%3}, [%4];"
        : "=r"(r[0]), "=r"(r[1]), "=r"(r[2]), "=r"(r[3]) : "r"(addr));
}
__device__ __forceinline__ void mma16816(float d[4], const uint32_t a[4],
                                         uint32_t b0, uint32_t b1) {
    asm volatile(
        "mma.sync.aligned.m16n8k16.row.col.f32.f16.f16.f32 "
        "{%0,%1,%2,%3}, {%4,%5,%6,%7}, {%8,%9}, {%0,%1,%2,%3};"
        : "+f"(d[0]), "+f"(d[1]), "+f"(d[2]), "+f"(d[3])
        : "r"(a[0]), "r"(a[1]), "r"(a[2]), "r"(a[3]), "r"(b0), "r"(b1));
}
__device__ __forceinline__ uint32_t f2h2(float x, float y) {
    __half2 h = __floats2half2_rn(x, y);
    return *reinterpret_cast<uint32_t*>(&h);
}
__device__ __forceinline__ float2 h22f2(uint32_t u) {
    __half2 h = *reinterpret_cast<__half2*>(&u);
    return __half22float2(h);
}
__device__ __forceinline__ void split_chunk(float4 a, float4 b,
                                            uint4& hi, uint4& lo) {
    hi = make_uint4(f2h2(a.x, a.y), f2h2(a.z, a.w), f2h2(b.x, b.y), f2h2(b.z, b.w));
    float2 r0 = h22f2(hi.x), r1 = h22f2(hi.y), r2 = h22f2(hi.z), r3 = h22f2(hi.w);
    lo = make_uint4(f2h2(a.x - r0.x, a.y - r0.y), f2h2(a.z - r1.x, a.w - r1.y),
                    f2h2(b.x - r2.x, b.y - r2.y), f2h2(b.z - r3.x, b.w - r3.y));
}
__device__ __forceinline__ uint32_t swadr(uint32_t base, uint32_t row, uint32_t chunk) {
    return base + row * 128u + ((chunk ^ (row & 7u)) << 4);
}
__device__ __forceinline__ void cp16(uint32_t dst, const void* src) {
    asm volatile("cp.async.ca.shared.global [%0], [%1], 16;"
                 :: "r"(dst), "l"(src) : "memory");
}
#define CP_COMMIT() asm volatile("cp.async.commit_group;" ::: "memory")
#define CP_WAIT(n)  asm volatile("cp.async.wait_group %0;" :: "n"(n) : "memory")

// ---------------------------------------------------------------------------
// Attention body (R11 version) — called from the fused kernel.
// ---------------------------------------------------------------------------
__device__ void attn_body(int unit, char* smraw, const float* __restrict__ Q)
{
    const uint32_t sb = smem_u32(smraw);
    const int tid  = threadIdx.x;
    const int wrp  = tid >> 5;
    const int lane = tid & 31;
    const int qt   = unit / KSPL;
    const int ks   = unit % KSPL;
    const int nt   = (NKT - ks + KSPL - 1) / KSPL;

    // ---- stage Q (2 threads per row), scaled by log2e, hi/lo fp16 ----
    {
        int r = tid >> 1, hc = tid & 1;
        int gr = qt * QTILE + r;
        const float4* src = (const float4*)(Q + (size_t)gr * DIM) + hc * 8;
        #pragma unroll
        for (int i = 0; i < 4; i++) {
            float4 a, b;
            if (gr < N_USERS) { a = src[2 * i]; b = src[2 * i + 1]; }
            else { a = make_float4(0.f, 0.f, 0.f, 0.f); b = a; }
            a.x *= LOG2E_F; a.y *= LOG2E_F; a.z *= LOG2E_F; a.w *= LOG2E_F;
            b.x *= LOG2E_F; b.y *= LOG2E_F; b.z *= LOG2E_F; b.w *= LOG2E_F;
            uint4 hi, lo;
            split_chunk(a, b, hi, lo);
            uint32_t c = hc * 4 + i;
            *(uint4*)(smraw + SQHI + swadr(0, r, c)) = hi;
            *(uint4*)(smraw + SQLO + swadr(0, r, c)) = lo;
        }
    }

    // ---- prologue: prefetch tiles 0 and 1 ----
    const int pr = tid >> 2, pq = tid & 3;
    #pragma unroll
    for (int pt = 0; pt < 2; pt++) {
        size_t key = (size_t)(ks + KSPL * pt) * KTILE + pr;
        const char* ghi = (const char*)g_kvhi + key * 128;
        const char* glo = (const char*)g_kvlo + key * 128;
        #pragma unroll
        for (int i = 0; i < 2; i++) {
            uint32_t c = pq * 2 + i;
            cp16(sb + SKB(pt) + swadr(0, pr, c),        ghi + c * 16);
            cp16(sb + SKB(pt) + 8192 + swadr(0, pr, c), glo + c * 16);
        }
        CP_COMMIT();
    }
    __syncthreads();

    // ---- Q fragments ----
    uint32_t qh[4][4], ql[4][4];
    #pragma unroll
    for (int kp = 0; kp < 4; kp++) {
        uint32_t row = 16 * wrp + ((lane >> 3) & 1) * 8 + (lane & 7);
        uint32_t ch  = 2 * kp + ((lane >> 4) & 1);
        ldsm4(qh[kp], swadr(sb + SQHI, row, ch));
        ldsm4(ql[kp], swadr(sb + SQLO, row, ch));
    }

    float o[8][4];
    float m[2], l[2];
    #pragma unroll
    for (int n = 0; n < 8; n++)
        #pragma unroll
        for (int k = 0; k < 4; k++) o[n][k] = 0.f;
    m[0] = m[1] = -CUDART_INF_F;
    l[0] = l[1] = 0.f;

    for (int t = 0; t < nt; t++) {
        const int kbase = (ks + KSPL * t) * KTILE;

        CP_WAIT(1);
        __syncthreads();

        if (t + 2 < nt) {
            size_t key = (size_t)(ks + KSPL * (t + 2)) * KTILE + pr;
            const char* ghi = (const char*)g_kvhi + key * 128;
            const char* glo = (const char*)g_kvlo + key * 128;
            uint32_t bb = SKB((t + 2) % 3);
            #pragma unroll
            for (int i = 0; i < 2; i++) {
                uint32_t c = pq * 2 + i;
                cp16(sb + bb + swadr(0, pr, c),        ghi + c * 16);
                cp16(sb + bb + 8192 + swadr(0, pr, c), glo + c * 16);
            }
        }
        CP_COMMIT();

        const uint32_t khi = sb + SKB(t % 3);
        const uint32_t klo = khi + 8192;

        float s[8][4];
        #pragma unroll
        for (int n = 0; n < 8; n++)
            #pragma unroll
            for (int k = 0; k < 4; k++) s[n][k] = 0.f;

        #pragma unroll
        for (int kp = 0; kp < 4; kp++) {
            #pragma unroll
            for (int p = 0; p < 4; p++) {
                uint32_t key = 16u * p + ((lane >> 4) & 1) * 8 + (lane & 7);
                uint32_t ch  = 2u * kp + ((lane >> 3) & 1);
                uint32_t bh[4], bl[4];
                ldsm4(bh, swadr(khi, key, ch));
                ldsm4(bl, swadr(klo, key, ch));
                mma16816(s[2*p],   qh[kp], bh[0], bh[1]);
                mma16816(s[2*p],   ql[kp], bh[0], bh[1]);
                mma16816(s[2*p],   qh[kp], bl[0], bl[1]);
                mma16816(s[2*p+1], qh[kp], bh[2], bh[3]);
                mma16816(s[2*p+1], ql[kp], bh[2], bh[3]);
                mma16816(s[2*p+1], qh[kp], bl[2], bl[3]);
            }
        }

        if (kbase + KTILE > N_NEWS) {
            #pragma unroll
            for (int n = 0; n < 8; n++) {
                int c0 = kbase + 8 * n + (lane & 3) * 2;
                #pragma unroll
                for (int d = 0; d < 2; d++) {
                    if (c0 + d >= N_NEWS) {
                        s[n][d]     = -CUDART_INF_F;
                        s[n][d + 2] = -CUDART_INF_F;
                    }
                }
            }
        }

        #pragma unroll
        for (int h = 0; h < 2; h++) {
            float mx = -CUDART_INF_F;
            #pragma unroll
            for (int n = 0; n < 8; n++)
                mx = fmaxf(mx, fmaxf(s[n][2*h], s[n][2*h+1]));
            mx = fmaxf(mx, __shfl_xor_sync(0xffffffffu, mx, 1));
            mx = fmaxf(mx, __shfl_xor_sync(0xffffffffu, mx, 2));
            if (mx > m[h]) {
                float sc = exp2f(m[h] - mx);
                m[h] = mx;
                l[h] *= sc;
                #pragma unroll
                for (int n = 0; n < 8; n++) {
                    o[n][2*h]   *= sc;
                    o[n][2*h+1] *= sc;
                }
            }
            #pragma unroll
            for (int n = 0; n < 8; n++) {
                float e0 = exp2f(s[n][2*h]   - m[h]);
                float e1 = exp2f(s[n][2*h+1] - m[h]);
                uint32_t u = f2h2(e0, e1);
                float2 er = h22f2(u);
                s[n][2*h]   = er.x;
                s[n][2*h+1] = er.y;
                l[h] += er.x + er.y;
            }
        }

        #pragma unroll
        for (int kk = 0; kk < 4; kk++) {
            uint32_t pa[4];
            pa[0] = f2h2(s[2*kk][0],   s[2*kk][1]);
            pa[1] = f2h2(s[2*kk][2],   s[2*kk][3]);
            pa[2] = f2h2(s[2*kk+1][0], s[2*kk+1][1]);
            pa[3] = f2h2(s[2*kk+1][2], s[2*kk+1][3]);
            #pragma unroll
            for (int p = 0; p < 4; p++) {
                uint32_t key = 16u * kk + ((lane >> 3) & 1) * 8 + (lane & 7);
                uint32_t ch  = 2u * p + ((lane >> 4) & 1);
                uint32_t vh[4];
                ldsm4t(vh, swadr(khi, key, ch));
                mma16816(o[2*p],   pa, vh[0], vh[1]);
                mma16816(o[2*p+1], pa, vh[2], vh[3]);
            }
        }
    }

    #pragma unroll
    for (int h = 0; h < 2; h++) {
        l[h] += __shfl_xor_sync(0xffffffffu, l[h], 1);
        l[h] += __shfl_xor_sync(0xffffffffu, l[h], 2);
    }

    const int g = lane >> 2;
    #pragma unroll
    for (int h = 0; h < 2; h++) {
        int row = 16 * wrp + 8 * h + g;
        float* pb = g_po + ((size_t)unit * 128 + row) * 64;
        #pragma unroll
        for (int n = 0; n < 8; n++) {
            int c = 8 * n + (lane & 3) * 2;
            *(float2*)(pb + c) = make_float2(o[n][2*h], o[n][2*h+1]);
        }
        if ((lane & 3) == 0) {
            g_pm[(size_t)unit * 128 + row] = m[h];
            g_pl[(size_t)unit * 128 + row] = l[h];
        }
    }
}

// ---------------------------------------------------------------------------
// Entity aggregation body (R11/R9 agg16, WRITE_KV=false) using dynamic smem.
// ---------------------------------------------------------------------------
__device__ void entity_body(int blk, char* smraw,
                            const float* __restrict__ ent,
                            const float* __restrict__ rel,
                            const int*   __restrict__ nbe,
                            const int*   __restrict__ nbr,
                            float* __restrict__ out)
{
    float* relS = (float*)smraw;                   // 8 KB
    int*   eS   = (int*)(smraw + 8192);            // 1.25 KB
    int*   rS   = eS + 16 * KNB;                   // 1.25 KB

    const int tid = threadIdx.x;
    for (int i = tid; i < N_RELS * DIM / 4; i += 256)
        ((float4*)relS)[i] = ((const float4*)rel)[i];
    const int rowbase = blk * 16;
    for (int i = tid; i < 16 * KNB; i += 256) {
        int rr = rowbase + i / KNB;
        bool ok = rr < N_ENT;
        eS[i] = ok ? __ldg(nbe + (size_t)rr * KNB + i % KNB) : 0;
        rS[i] = ok ? __ldg(nbr + (size_t)rr * KNB + i % KNB) : 0;
    }
    __syncthreads();

    const int wrp  = tid >> 5;
    const int lane = tid & 31;
    const int rloc = wrp * 2 + (lane >> 4);
    const int sl   = lane & 15;
    const int w    = rowbase + rloc;
    if (w >= N_ENT) return;

    const float4 h = ((const float4*)(ent + (size_t)w * DIM))[sl];   // head == ent
    const int* re = eS + rloc * KNB;
    const int* rr = rS + rloc * KNB;

    float4 sx = make_float4(0.f, 0.f, 0.f, 0.f);
    #pragma unroll 4
    for (int k = 0; k < KNB; k++) {
        float4 a = ((const float4*)(relS + rr[k] * DIM))[sl];
        sx.x += a.x * a.x; sx.y += a.y * a.y;
        sx.z += a.z * a.z; sx.w += a.w * a.w;
    }
    float4 hn = make_float4(fabsf(h.x) * sqrtf(sx.x), fabsf(h.y) * sqrtf(sx.y),
                            fabsf(h.z) * sqrtf(sx.z), fabsf(h.w) * sqrtf(sx.w));

    float m = 0.f, l = 0.f;
    float4 acc = make_float4(0.f, 0.f, 0.f, 0.f);
    #pragma unroll 4
    for (int k = 0; k < KNB; k++) {
        float4 ra = ((const float4*)(relS + rr[k] * DIM))[sl];
        float4 t  = ((const float4*)(ent + (size_t)re[k] * DIM))[sl];
        float p = t.x * ra.x * hn.x + t.y * ra.y * hn.y
                + t.z * ra.z * hn.z + t.w * ra.w * hn.w;
        p += __shfl_xor_sync(0xffffffffu, p, 1);
        p += __shfl_xor_sync(0xffffffffu, p, 2);
        p += __shfl_xor_sync(0xffffffffu, p, 4);
        p += __shfl_xor_sync(0xffffffffu, p, 8);
        float a2 = p * p;
        if (k == 0) {
            m = a2; l = 1.f; acc = t;
        } else {
            float mn = fmaxf(m, a2);
            float sc = __expf(m - mn);
            float e  = __expf(a2 - mn);
            l = l * sc + e;
            acc.x = acc.x * sc + e * t.x;
            acc.y = acc.y * sc + e * t.y;
            acc.z = acc.z * sc + e * t.z;
            acc.w = acc.w * sc + e * t.w;
            m = mn;
        }
    }
    float inv = 1.f / l;
    ((float4*)(out + (size_t)w * DIM))[sl] =
        make_float4(acc.x * inv, acc.y * inv, acc.z * inv, acc.w * inv);
}

// ---------------------------------------------------------------------------
// Fused kernel: 1 attn block per INTERLEAVE blocks, rest entity.
// ---------------------------------------------------------------------------
__global__ void __launch_bounds__(256, 2)
fused_kernel(const float* __restrict__ Q,
             const float* __restrict__ ent,
             const float* __restrict__ rel,
             const int*   __restrict__ nbe,
             const int*   __restrict__ nbr,
             float* __restrict__ ent_out)
{
    extern __shared__ char smraw[];
    const int bid = blockIdx.x;

    int attn_unit = -1, ent_blk = -1;
    if (bid < ATT_UNITS * INTERLEAVE) {
        if (bid % INTERLEAVE == 0) attn_unit = bid / INTERLEAVE;
        else                       ent_blk   = bid - bid / INTERLEAVE - 1;
    } else {
        ent_blk = bid - ATT_UNITS;
    }

    if (attn_unit >= 0) attn_body(attn_unit, smraw, Q);
    else                entity_body(ent_blk, smraw, ent, rel, nbe, nbr, ent_out);
}

// ---------------------------------------------------------------------------
// News aggregation (standalone, writes KV split; R11 agg16 WRITE_KV=true).
// ---------------------------------------------------------------------------
__global__ void __launch_bounds__(256, 2) news_agg_kernel(
    const float* __restrict__ head,
    const float* __restrict__ ent,
    const float* __restrict__ rel,
    const int*   __restrict__ nbe,
    const int*   __restrict__ nbr,
    float* __restrict__ out)
{
    __shared__ float relS[N_RELS * DIM];
    __shared__ int   eS[16 * KNB];
    __shared__ int   rS[16 * KNB];

    const int tid = threadIdx.x;
    for (int i = tid; i < N_RELS * DIM / 4; i += 256)
        ((float4*)relS)[i] = ((const float4*)rel)[i];
    const int rowbase = blockIdx.x * 16;
    for (int i = tid; i < 16 * KNB; i += 256) {
        int rr = rowbase + i / KNB;
        bool ok = rr < N_NEWS;
        eS[i] = ok ? __ldg(nbe + (size_t)rr * KNB + i % KNB) : 0;
        rS[i] = ok ? __ldg(nbr + (size_t)rr * KNB + i % KNB) : 0;
    }
    __syncthreads();

    const int wrp  = tid >> 5;
    const int lane = tid & 31;
    const int rloc = wrp * 2 + (lane >> 4);
    const int sl   = lane & 15;
    const int w    = rowbase + rloc;
    if (w >= KVROWS) return;

    float4 v = make_float4(0.f, 0.f, 0.f, 0.f);

    if (w < N_NEWS) {
        const float4 h = ((const float4*)(head + (size_t)w * DIM))[sl];
        const int* re = eS + rloc * KNB;
        const int* rr = rS + rloc * KNB;

        float4 sx = make_float4(0.f, 0.f, 0.f, 0.f);
        #pragma unroll 4
        for (int k = 0; k < KNB; k++) {
            float4 a = ((const float4*)(relS + rr[k] * DIM))[sl];
            sx.x += a.x * a.x; sx.y += a.y * a.y;
            sx.z += a.z * a.z; sx.w += a.w * a.w;
        }
        float4 hn = make_float4(fabsf(h.x) * sqrtf(sx.x), fabsf(h.y) * sqrtf(sx.y),
                                fabsf(h.z) * sqrtf(sx.z), fabsf(h.w) * sqrtf(sx.w));

        float m = 0.f, l = 0.f;
        float4 acc = make_float4(0.f, 0.f, 0.f, 0.f);
        #pragma unroll 4
        for (int k = 0; k < KNB; k++) {
            float4 ra = ((const float4*)(relS + rr[k] * DIM))[sl];
            float4 t  = ((const float4*)(ent + (size_t)re[k] * DIM))[sl];
            float p = t.x * ra.x * hn.x + t.y * ra.y * hn.y
                    + t.z * ra.z * hn.z + t.w * ra.w * hn.w;
            p += __shfl_xor_sync(0xffffffffu, p, 1);
            p += __shfl_xor_sync(0xffffffffu, p, 2);
            p += __shfl_xor_sync(0xffffffffu, p, 4);
            p += __shfl_xor_sync(0xffffffffu, p, 8);
            float a2 = p * p;
            if (k == 0) {
                m = a2; l = 1.f; acc = t;
            } else {
                float mn = fmaxf(m, a2);
                float sc = __expf(m - mn);
                float e  = __expf(a2 - mn);
                l = l * sc + e;
                acc.x = acc.x * sc + e * t.x;
                acc.y = acc.y * sc + e * t.y;
                acc.z = acc.z * sc + e * t.z;
                acc.w = acc.w * sc + e * t.w;
                m = mn;
            }
        }
        float inv = 1.f / l;
        v = make_float4(acc.x * inv, acc.y * inv, acc.z * inv, acc.w * inv);
        ((float4*)(out + (size_t)w * DIM))[sl] = v;
    }

    // KV hi/lo split, scaled by log2e on the K side? No: Q carries log2e.
    uint32_t h0 = f2h2(v.x, v.y), h1 = f2h2(v.z, v.w);
    float2 q0 = h22f2(h0), q1 = h22f2(h1);
    uint32_t l0 = f2h2(v.x - q0.x, v.y - q0.y);
    uint32_t l1 = f2h2(v.z - q1.x, v.w - q1.y);
    *(uint2*)((char*)g_kvhi + ((size_t)w * DIM + sl * 4) * 2) = make_uint2(h0, h1);
    *(uint2*)((char*)g_kvlo + ((size_t)w * DIM + sl * 4) * 2) = make_uint2(l0, l1);
}

// ---------------------------------------------------------------------------
// CSR build + gather + combine (unchanged).
// ---------------------------------------------------------------------------
__global__ void __launch_bounds__(256) hist_kernel(const int* __restrict__ rows)
{
    int i = blockIdx.x * 256 + threadIdx.x;
    if (i < NNZ_CNT) atomicAdd(&g_cnt[__ldg(rows + i)], 1);
}

__global__ void __launch_bounds__(1024) scan_kernel()
{
    __shared__ int wsum[32];
    __shared__ int carry;
    const int tid = threadIdx.x, lane = tid & 31, wid = tid >> 5;
    if (tid == 0) { carry = 0; g_off[0] = 0; }
    __syncthreads();
    for (int base = 0; base < N_USERS; base += 1024) {
        int i = base + tid;
        int v = (i < N_USERS) ? g_cnt[i] : 0;
        #pragma unroll
        for (int d = 1; d < 32; d <<= 1) {
            int y = __shfl_up_sync(0xffffffffu, v, d);
            if (lane >= d) v += y;
        }
        if (lane == 31) wsum[wid] = v;
        __syncthreads();
        if (wid == 0) {
            int w = wsum[lane];
            #pragma unroll
            for (int d = 1; d < 32; d <<= 1) {
                int y = __shfl_up_sync(0xffffffffu, w, d);
                if (lane >= d) w += y;
            }
            wsum[lane] = w;
        }
        __syncthreads();
        int incl = v + (wid ? wsum[wid - 1] : 0) + carry;
        if (i < N_USERS) g_off[i + 1] = incl;
        __syncthreads();
        if (tid == 1023) carry = incl;
        __syncthreads();
    }
}

__global__ void __launch_bounds__(256) scatter_kernel(
    const int* __restrict__ rows,
    const int* __restrict__ cols,
    const float* __restrict__ vals)
{
    int i = blockIdx.x * 256 + threadIdx.x;
    if (i >= NNZ_CNT) return;
    int r = __ldg(rows + i);
    int pos = g_off[r] + atomicAdd(&g_cnt[r], 1);
    g_pcv[pos] = make_int2(__ldg(cols + i), __float_as_int(__ldg(vals + i)));
}

__global__ void __launch_bounds__(256) gather_kernel(
    const float* __restrict__ news_agg,
    float* __restrict__ user_seg)
{
    int w    = (blockIdx.x * 256 + threadIdx.x) >> 5;
    int lane = threadIdx.x & 31;
    if (w >= N_USERS) return;
    int j = g_off[w], e = g_off[w + 1];
    float2 acc = make_float2(0.f, 0.f);
    for (; j + 4 <= e; j += 4) {
        int2 c0 = g_pcv[j], c1 = g_pcv[j+1], c2 = g_pcv[j+2], c3 = g_pcv[j+3];
        float2 a = *(const float2*)(news_agg + (size_t)c0.x * DIM + 2 * lane);
        float2 b = *(const float2*)(news_agg + (size_t)c1.x * DIM + 2 * lane);
        float2 c = *(const float2*)(news_agg + (size_t)c2.x * DIM + 2 * lane);
        float2 d = *(const float2*)(news_agg + (size_t)c3.x * DIM + 2 * lane);
        float v0 = __int_as_float(c0.y), v1 = __int_as_float(c1.y);
        float v2 = __int_as_float(c2.y), v3 = __int_as_float(c3.y);
        acc.x += v0*a.x + v1*b.x + v2*c.x + v3*d.x;
        acc.y += v0*a.y + v1*b.y + v2*c.y + v3*d.y;
    }
    for (; j < e; j++) {
        int2 cv = g_pcv[j];
        float2 a = *(const float2*)(news_agg + (size_t)cv.x * DIM + 2 * lane);
        float v = __int_as_float(cv.y);
        acc.x += v * a.x;
        acc.y += v * a.y;
    }
    *(float2*)(user_seg + (size_t)w * DIM + 2 * lane) = acc;
}

__global__ void __launch_bounds__(256) combine_kernel(float* __restrict__ user_out)
{
    int w    = (blockIdx.x * blockDim.x + threadIdx.x) >> 5;
    int lane = threadIdx.x & 31;
    if (w >= N_USERS) return;
    int qt = w >> 7, r = w & 127;

    float M = -CUDART_INF_F;
    float ms[KSPL], ls[KSPL];
    #pragma unroll
    for (int s = 0; s < KSPL; s++) {
        size_t u = (size_t)(qt * KSPL + s);
        ms[s] = g_pm[u * 128 + r];
        ls[s] = g_pl[u * 128 + r];
        M = fmaxf(M, ms[s]);
    }
    float L = 0.f, ax = 0.f, ay = 0.f;
    #pragma unroll
    for (int s = 0; s < KSPL; s++) {
        size_t u = (size_t)(qt * KSPL + s);
        float e = exp2f(ms[s] - M);
        L += e * ls[s];
        float2 o2 = ((const float2*)(g_po + (u * 128 + r) * 64))[lane];
        ax += e * o2.x;
        ay += e * o2.y;
    }
    float inv = 1.f / L;
    float2* up = (float2*)(user_out + (size_t)w * DIM);
    float2 sg = up[lane];
    up[lane] = make_float2(sg.x + ax * inv * sg.x,
                           sg.y + ay * inv * sg.y);
}

// ---------------------------------------------------------------------------
// Launch: s0: news -> fused(attn+entity) -> (join gather) combine;
//         s1: CSR -> (wait news) gather.
// ---------------------------------------------------------------------------
extern "C" void kernel_launch(void* const* d_in, const int* in_sizes, int n_in,
                              void* d_out, int out_size)
{
    const float* user_emb = (const float*)d_in[0];
    const float* news_emb = (const float*)d_in[1];
    const float* ent_emb  = (const float*)d_in[2];
    const float* rel_emb  = (const float*)d_in[3];
    const int*   news_ent = (const int*)d_in[4];
    const int*   news_rel = (const int*)d_in[5];
    const int*   nb_ent   = (const int*)d_in[6];
    const int*   nb_rel   = (const int*)d_in[7];
    const int*   irows    = (const int*)d_in[8];
    const int*   icols    = (const int*)d_in[9];
    const float* ivals    = (const float*)d_in[10];

    float* out      = (float*)d_out;
    float* news_out = out;
    float* ent_out  = out + (size_t)N_NEWS * DIM;
    float* user_out = ent_out + (size_t)N_ENT * DIM;

    static cudaStream_t s0 = nullptr, s1 = nullptr;
    static cudaEvent_t  ev0, evNews, evG, evDone;
    if (!s0) {
        int lo, hi;
        cudaDeviceGetStreamPriorityRange(&lo, &hi);
        cudaStreamCreateWithPriority(&s0, cudaStreamNonBlocking, hi);
        cudaStreamCreateWithPriority(&s1, cudaStreamNonBlocking, lo);
        cudaEventCreateWithFlags(&ev0,    cudaEventDisableTiming);
        cudaEventCreateWithFlags(&evNews, cudaEventDisableTiming);
        cudaEventCreateWithFlags(&evG,    cudaEventDisableTiming);
        cudaEventCreateWithFlags(&evDone, cudaEventDisableTiming);
        cudaFuncSetAttribute(fused_kernel,
                             cudaFuncAttributeMaxDynamicSharedMemorySize, SMEM_ATT);
    }

    void* cnt_ptr = nullptr;
    cudaGetSymbolAddress(&cnt_ptr, g_cnt);

    cudaEventRecord(ev0, 0);
    cudaStreamWaitEvent(s0, ev0, 0);
    cudaStreamWaitEvent(s1, ev0, 0);

    // s0: news agg -> fused attn+entity
    news_agg_kernel<<<(KVROWS + 15) / 16, 256, 0, s0>>>(
        news_emb, ent_emb, rel_emb, news_ent, news_rel, news_out);
    cudaEventRecord(evNews, s0);
    fused_kernel<<<FUSE_BLOCKS, 256, SMEM_ATT, s0>>>(
        user_emb, ent_emb, rel_emb, nb_ent, nb_rel, ent_out);

    // s1: CSR build, then gather after news agg
    cudaMemsetAsync(cnt_ptr, 0, N_USERS * sizeof(int), s1);
    hist_kernel<<<(NNZ_CNT + 255) / 256, 256, 0, s1>>>(irows);
    scan_kernel<<<1, 1024, 0, s1>>>();
    cudaMemsetAsync(cnt_ptr, 0, N_USERS * sizeof(int), s1);
    scatter_kernel<<<(NNZ_CNT + 255) / 256, 256, 0, s1>>>(irows, icols, ivals);
    cudaStreamWaitEvent(s1, evNews, 0);
    gather_kernel<<<(N_USERS * 32 + 255) / 256, 256, 0, s1>>>(news_out, user_out);
    cudaEventRecord(evG, s1);

    // s0: join gather, run combine
    cudaStreamWaitEvent(s0, evG, 0);
    combine_kernel<<<(N_USERS + 7) / 8, 256, 0, s0>>>(user_out);
    cudaEventRecord(evDone, s0);

    cudaStreamWaitEvent(0, evDone, 0);
}

// round 13
// speedup vs baseline: 1.2934x; 1.2934x over previous
#include <cuda_runtime.h>
#include <cuda_fp16.h>
#include <math_constants.h>
#include <cstdint>
#include <cstddef>

#define N_USERS 10000
#define N_NEWS  10000
#define N_ENT   100000
#define N_RELS  32
#define DIM     64
#define KNB     20
#define NNZ_CNT 500000
#define LOG2E_F 1.44269504088896340736f

// -------------------- attention (mma.sync fp16) config ---------------------
#define QTILE   128
#define KTILE   64
#define QTILES  79                  // ceil(10000/128)
#define NKT     157                 // ceil(10000/64)
#define KVROWS  (NKT * KTILE)       // 10048 (48 zero-pad rows)
#define KSPL    15
#define ATT_UNITS (QTILES * KSPL)   // 1185

__device__ float g_po[(size_t)ATT_UNITS * 128 * 64];
__device__ float g_pl[(size_t)ATT_UNITS * 128];
__device__ float g_pm[(size_t)ATT_UNITS * 128];

// pre-split KV in fp16 (hi only; 2-term S split keeps Q_lo x K_hi)
__device__ __half g_kvhi[(size_t)KVROWS * DIM];

// CSR scratch for the user segment-sum
__device__ int  g_cnt[N_USERS];
__device__ int  g_off[N_USERS + 1];
__device__ int2 g_pcv[NNZ_CNT];       // (col, val-bits) sorted by row

// smem map (bytes): Q hi/lo 16KB each; 3 K buffers of 8KB (hi only)
#define SQHI  0
#define SQLO  16384
#define SKB(b)   (32768 + (b) * 8192)
#define SMEM_ATT 57344

// ----------------------------- helpers -------------------------------------
__device__ __forceinline__ uint32_t smem_u32(const void* p) {
    uint32_t a;
    asm("{ .reg .u64 t; cvta.to.shared.u64 t, %1; cvt.u32.u64 %0, t; }"
        : "=r"(a) : "l"(p));
    return a;
}
__device__ __forceinline__ void ldsm4(uint32_t r[4], uint32_t addr) {
    asm volatile("ldmatrix.sync.aligned.m8n8.x4.shared.b16 {%0,%1,%2,%3}, [%4];"
        : "=r"(r[0]), "=r"(r[1]), "=r"(r[2]), "=r"(r[3]) : "r"(addr));
}
__device__ __forceinline__ void ldsm4t(uint32_t r[4], uint32_t addr) {
    asm volatile("ldmatrix.sync.aligned.m8n8.x4.trans.shared.b16 {%0,%1,%2,%3}, [%4];"
        : "=r"(r[0]), "=r"(r[1]), "=r"(r[2]), "=r"(r[3]) : "r"(addr));
}
__device__ __forceinline__ void mma16816(float d[4], const uint32_t a[4],
                                         uint32_t b0, uint32_t b1) {
    asm volatile(
        "mma.sync.aligned.m16n8k16.row.col.f32.f16.f16.f32 "
        "{%0,%1,%2,%3}, {%4,%5,%6,%7}, {%8,%9}, {%0,%1,%2,%3};"
        : "+f"(d[0]), "+f"(d[1]), "+f"(d[2]), "+f"(d[3])
        : "r"(a[0]), "r"(a[1]), "r"(a[2]), "r"(a[3]), "r"(b0), "r"(b1));
}
__device__ __forceinline__ uint32_t f2h2(float x, float y) {
    __half2 h = __floats2half2_rn(x, y);
    return *reinterpret_cast<uint32_t*>(&h);
}
__device__ __forceinline__ float2 h22f2(uint32_t u) {
    __half2 h = *reinterpret_cast<__half2*>(&u);
    return __half22float2(h);
}
__device__ __forceinline__ void split_chunk(float4 a, float4 b,
                                            uint4& hi, uint4& lo) {
    hi = make_uint4(f2h2(a.x, a.y), f2h2(a.z, a.w), f2h2(b.x, b.y), f2h2(b.z, b.w));
    float2 r0 = h22f2(hi.x), r1 = h22f2(hi.y), r2 = h22f2(hi.z), r3 = h22f2(hi.w);
    lo = make_uint4(f2h2(a.x - r0.x, a.y - r0.y), f2h2(a.z - r1.x, a.w - r1.y),
                    f2h2(b.x - r2.x, b.y - r2.y), f2h2(b.z - r3.x, b.w - r3.y));
}
__device__ __forceinline__ uint32_t swadr(uint32_t base, uint32_t row, uint32_t chunk) {
    return base + row * 128u + ((chunk ^ (row & 7u)) << 4);
}
__device__ __forceinline__ void cp16(uint32_t dst, const void* src) {
    asm volatile("cp.async.ca.shared.global [%0], [%1], 16;"
                 :: "r"(dst), "l"(src) : "memory");
}
#define CP_COMMIT() asm volatile("cp.async.commit_group;" ::: "memory")
#define CP_WAIT(n)  asm volatile("cp.async.wait_group %0;" :: "n"(n) : "memory")

// ---------------------------------------------------------------------------
// FA2 on mma.sync fp16. 2-term S split (qhi*khi + qlo*khi); O = P @ V_hi.
// Q pre-scaled by log2e -> exp2f softmax; conditional O-rescale.
// ---------------------------------------------------------------------------
__global__ void __launch_bounds__(256, 2)
attn_mma_kernel(const float* __restrict__ Q)
{
    extern __shared__ char smraw[];
    const uint32_t sb = smem_u32(smraw);
    const int tid  = threadIdx.x;
    const int wrp  = tid >> 5;
    const int lane = tid & 31;
    const int qt   = blockIdx.x / KSPL;
    const int ks   = blockIdx.x % KSPL;
    const int nt   = (NKT - ks + KSPL - 1) / KSPL;

    // ---- stage Q (2 threads per row), scaled by log2e, hi/lo fp16 ----
    {
        int r = tid >> 1, hc = tid & 1;
        int gr = qt * QTILE + r;
        const float4* src = (const float4*)(Q + (size_t)gr * DIM) + hc * 8;
        #pragma unroll
        for (int i = 0; i < 4; i++) {
            float4 a, b;
            if (gr < N_USERS) { a = src[2 * i]; b = src[2 * i + 1]; }
            else { a = make_float4(0.f, 0.f, 0.f, 0.f); b = a; }
            a.x *= LOG2E_F; a.y *= LOG2E_F; a.z *= LOG2E_F; a.w *= LOG2E_F;
            b.x *= LOG2E_F; b.y *= LOG2E_F; b.z *= LOG2E_F; b.w *= LOG2E_F;
            uint4 hi, lo;
            split_chunk(a, b, hi, lo);
            uint32_t c = hc * 4 + i;
            *(uint4*)(smraw + SQHI + swadr(0, r, c)) = hi;
            *(uint4*)(smraw + SQLO + swadr(0, r, c)) = lo;
        }
    }

    // ---- prologue: prefetch tiles 0 and 1 (4 threads per key row) ----
    const int pr = tid >> 2, pq = tid & 3;
    #pragma unroll
    for (int pt = 0; pt < 2; pt++) {
        size_t key = (size_t)(ks + KSPL * pt) * KTILE + pr;
        const char* ghi = (const char*)g_kvhi + key * 128;
        #pragma unroll
        for (int i = 0; i < 2; i++) {
            uint32_t c = pq * 2 + i;
            cp16(sb + SKB(pt) + swadr(0, pr, c), ghi + c * 16);
        }
        CP_COMMIT();
    }
    __syncthreads();     // Q stores visible

    // ---- Q fragments ----
    uint32_t qh[4][4], ql[4][4];
    #pragma unroll
    for (int kp = 0; kp < 4; kp++) {
        uint32_t row = 16 * wrp + ((lane >> 3) & 1) * 8 + (lane & 7);
        uint32_t ch  = 2 * kp + ((lane >> 4) & 1);
        ldsm4(qh[kp], swadr(sb + SQHI, row, ch));
        ldsm4(ql[kp], swadr(sb + SQLO, row, ch));
    }

    float o[8][4];
    float m[2], l[2];
    #pragma unroll
    for (int n = 0; n < 8; n++)
        #pragma unroll
        for (int k = 0; k < 4; k++) o[n][k] = 0.f;
    m[0] = m[1] = -CUDART_INF_F;
    l[0] = l[1] = 0.f;

    for (int t = 0; t < nt; t++) {
        const int kbase = (ks + KSPL * t) * KTILE;

        CP_WAIT(1);
        __syncthreads();

        if (t + 2 < nt) {
            size_t key = (size_t)(ks + KSPL * (t + 2)) * KTILE + pr;
            const char* ghi = (const char*)g_kvhi + key * 128;
            uint32_t bb = SKB((t + 2) % 3);
            #pragma unroll
            for (int i = 0; i < 2; i++) {
                uint32_t c = pq * 2 + i;
                cp16(sb + bb + swadr(0, pr, c), ghi + c * 16);
            }
        }
        CP_COMMIT();

        const uint32_t khi = sb + SKB(t % 3);

        // ---- S = Q @ K^T (2-term split: qhi + qlo, K_hi only) ----
        float s[8][4];
        #pragma unroll
        for (int n = 0; n < 8; n++)
            #pragma unroll
            for (int k = 0; k < 4; k++) s[n][k] = 0.f;

        #pragma unroll
        for (int kp = 0; kp < 4; kp++) {
            #pragma unroll
            for (int p = 0; p < 4; p++) {
                uint32_t key = 16u * p + ((lane >> 4) & 1) * 8 + (lane & 7);
                uint32_t ch  = 2u * kp + ((lane >> 3) & 1);
                uint32_t bh[4];
                ldsm4(bh, swadr(khi, key, ch));
                mma16816(s[2*p],   qh[kp], bh[0], bh[1]);
                mma16816(s[2*p],   ql[kp], bh[0], bh[1]);
                mma16816(s[2*p+1], qh[kp], bh[2], bh[3]);
                mma16816(s[2*p+1], ql[kp], bh[2], bh[3]);
            }
        }

        // ---- mask tail keys ----
        if (kbase + KTILE > N_NEWS) {
            #pragma unroll
            for (int n = 0; n < 8; n++) {
                int c0 = kbase + 8 * n + (lane & 3) * 2;
                #pragma unroll
                for (int d = 0; d < 2; d++) {
                    if (c0 + d >= N_NEWS) {
                        s[n][d]     = -CUDART_INF_F;
                        s[n][d + 2] = -CUDART_INF_F;
                    }
                }
            }
        }

        // ---- online softmax (log2 domain) ----
        #pragma unroll
        for (int h = 0; h < 2; h++) {
            float mx = -CUDART_INF_F;
            #pragma unroll
            for (int n = 0; n < 8; n++)
                mx = fmaxf(mx, fmaxf(s[n][2*h], s[n][2*h+1]));
            mx = fmaxf(mx, __shfl_xor_sync(0xffffffffu, mx, 1));
            mx = fmaxf(mx, __shfl_xor_sync(0xffffffffu, mx, 2));
            if (mx > m[h]) {
                float sc = exp2f(m[h] - mx);
                m[h] = mx;
                l[h] *= sc;
                #pragma unroll
                for (int n = 0; n < 8; n++) {
                    o[n][2*h]   *= sc;
                    o[n][2*h+1] *= sc;
                }
            }
            #pragma unroll
            for (int n = 0; n < 8; n++) {
                float e0 = exp2f(s[n][2*h]   - m[h]);
                float e1 = exp2f(s[n][2*h+1] - m[h]);
                uint32_t u = f2h2(e0, e1);
                float2 er = h22f2(u);
                s[n][2*h]   = er.x;
                s[n][2*h+1] = er.y;
                l[h] += er.x + er.y;
            }
        }

        // ---- O += P @ V_hi ----
        #pragma unroll
        for (int kk = 0; kk < 4; kk++) {
            uint32_t pa[4];
            pa[0] = f2h2(s[2*kk][0],   s[2*kk][1]);
            pa[1] = f2h2(s[2*kk][2],   s[2*kk][3]);
            pa[2] = f2h2(s[2*kk+1][0], s[2*kk+1][1]);
            pa[3] = f2h2(s[2*kk+1][2], s[2*kk+1][3]);
            #pragma unroll
            for (int p = 0; p < 4; p++) {
                uint32_t key = 16u * kk + ((lane >> 3) & 1) * 8 + (lane & 7);
                uint32_t ch  = 2u * p + ((lane >> 4) & 1);
                uint32_t vh[4];
                ldsm4t(vh, swadr(khi, key, ch));
                mma16816(o[2*p],   pa, vh[0], vh[1]);
                mma16816(o[2*p+1], pa, vh[2], vh[3]);
            }
        }
    }

    // ---- reduce l across the 4 lanes of each row ----
    #pragma unroll
    for (int h = 0; h < 2; h++) {
        l[h] += __shfl_xor_sync(0xffffffffu, l[h], 1);
        l[h] += __shfl_xor_sync(0xffffffffu, l[h], 2);
    }

    // ---- write partial ----
    const int g = lane >> 2;
    #pragma unroll
    for (int h = 0; h < 2; h++) {
        int row = 16 * wrp + 8 * h + g;
        float* pb = g_po + ((size_t)blockIdx.x * 128 + row) * 64;
        #pragma unroll
        for (int n = 0; n < 8; n++) {
            int c = 8 * n + (lane & 3) * 2;
            *(float2*)(pb + c) = make_float2(o[n][2*h], o[n][2*h+1]);
        }
        if ((lane & 3) == 0) {
            g_pm[(size_t)blockIdx.x * 128 + row] = m[h];
            g_pl[(size_t)blockIdx.x * 128 + row] = l[h];
        }
    }
}

// ---------------------------------------------------------------------------
// Aggregation (R11/R9): 2 rows/warp, 16 lanes/row, float4 per lane,
// online softmax. KV write is hi-only now.
// ---------------------------------------------------------------------------
template<bool WRITE_KV>
__global__ void __launch_bounds__(256, 2) agg16_kernel(
    const float* __restrict__ head,
    const float* __restrict__ ent,
    const float* __restrict__ rel,
    const int*   __restrict__ nbe,
    const int*   __restrict__ nbr,
    float* __restrict__ out, int N, int Ntotal)
{
    __shared__ float relS[N_RELS * DIM];
    __shared__ int   eS[16 * KNB];
    __shared__ int   rS[16 * KNB];

    const int tid = threadIdx.x;
    for (int i = tid; i < N_RELS * DIM / 4; i += 256)
        ((float4*)relS)[i] = ((const float4*)rel)[i];
    const int rowbase = blockIdx.x * 16;
    for (int i = tid; i < 16 * KNB; i += 256) {
        int rr = rowbase + i / KNB;
        bool ok = rr < N;
        eS[i] = ok ? __ldg(nbe + (size_t)rr * KNB + i % KNB) : 0;
        rS[i] = ok ? __ldg(nbr + (size_t)rr * KNB + i % KNB) : 0;
    }
    __syncthreads();

    const int wrp  = tid >> 5;
    const int lane = tid & 31;
    const int rloc = wrp * 2 + (lane >> 4);
    const int sl   = lane & 15;
    const int w    = rowbase + rloc;
    if (w >= Ntotal) return;

    float4 v = make_float4(0.f, 0.f, 0.f, 0.f);

    if (w < N) {
        const float4 h = ((const float4*)(head + (size_t)w * DIM))[sl];
        const int* re = eS + rloc * KNB;
        const int* rr = rS + rloc * KNB;

        float4 sx = make_float4(0.f, 0.f, 0.f, 0.f);
        #pragma unroll 4
        for (int k = 0; k < KNB; k++) {
            float4 a = ((const float4*)(relS + rr[k] * DIM))[sl];
            sx.x += a.x * a.x; sx.y += a.y * a.y;
            sx.z += a.z * a.z; sx.w += a.w * a.w;
        }
        float4 hn = make_float4(fabsf(h.x) * sqrtf(sx.x), fabsf(h.y) * sqrtf(sx.y),
                                fabsf(h.z) * sqrtf(sx.z), fabsf(h.w) * sqrtf(sx.w));

        float m = 0.f, l = 0.f;
        float4 acc = make_float4(0.f, 0.f, 0.f, 0.f);
        #pragma unroll 4
        for (int k = 0; k < KNB; k++) {
            float4 ra = ((const float4*)(relS + rr[k] * DIM))[sl];
            float4 t  = ((const float4*)(ent + (size_t)re[k] * DIM))[sl];
            float p = t.x * ra.x * hn.x + t.y * ra.y * hn.y
                    + t.z * ra.z * hn.z + t.w * ra.w * hn.w;
            p += __shfl_xor_sync(0xffffffffu, p, 1);
            p += __shfl_xor_sync(0xffffffffu, p, 2);
            p += __shfl_xor_sync(0xffffffffu, p, 4);
            p += __shfl_xor_sync(0xffffffffu, p, 8);
            float a2 = p * p;
            if (k == 0) {
                m = a2; l = 1.f; acc = t;
            } else {
                float mn = fmaxf(m, a2);
                float sc = __expf(m - mn);
                float e  = __expf(a2 - mn);
                l = l * sc + e;
                acc.x = acc.x * sc + e * t.x;
                acc.y = acc.y * sc + e * t.y;
                acc.z = acc.z * sc + e * t.z;
                acc.w = acc.w * sc + e * t.w;
                m = mn;
            }
        }
        float inv = 1.f / l;
        v = make_float4(acc.x * inv, acc.y * inv, acc.z * inv, acc.w * inv);
        ((float4*)(out + (size_t)w * DIM))[sl] = v;
    }

    if (WRITE_KV) {
        uint32_t h0 = f2h2(v.x, v.y), h1 = f2h2(v.z, v.w);
        *(uint2*)((char*)g_kvhi + ((size_t)w * DIM + sl * 4) * 2) = make_uint2(h0, h1);
    }
}

// ---------------------------------------------------------------------------
// CSR build + gather + combine (unchanged).
// ---------------------------------------------------------------------------
__global__ void __launch_bounds__(256) hist_kernel(const int* __restrict__ rows)
{
    int i = blockIdx.x * 256 + threadIdx.x;
    if (i < NNZ_CNT) atomicAdd(&g_cnt[__ldg(rows + i)], 1);
}

__global__ void __launch_bounds__(1024) scan_kernel()
{
    __shared__ int wsum[32];
    __shared__ int carry;
    const int tid = threadIdx.x, lane = tid & 31, wid = tid >> 5;
    if (tid == 0) { carry = 0; g_off[0] = 0; }
    __syncthreads();
    for (int base = 0; base < N_USERS; base += 1024) {
        int i = base + tid;
        int v = (i < N_USERS) ? g_cnt[i] : 0;
        #pragma unroll
        for (int d = 1; d < 32; d <<= 1) {
            int y = __shfl_up_sync(0xffffffffu, v, d);
            if (lane >= d) v += y;
        }
        if (lane == 31) wsum[wid] = v;
        __syncthreads();
        if (wid == 0) {
            int w = wsum[lane];
            #pragma unroll
            for (int d = 1; d < 32; d <<= 1) {
                int y = __shfl_up_sync(0xffffffffu, w, d);
                if (lane >= d) w += y;
            }
            wsum[lane] = w;
        }
        __syncthreads();
        int incl = v + (wid ? wsum[wid - 1] : 0) + carry;
        if (i < N_USERS) g_off[i + 1] = incl;
        __syncthreads();
        if (tid == 1023) carry = incl;
        __syncthreads();
    }
}

__global__ void __launch_bounds__(256) scatter_kernel(
    const int* __restrict__ rows,
    const int* __restrict__ cols,
    const float* __restrict__ vals)
{
    int i = blockIdx.x * 256 + threadIdx.x;
    if (i >= NNZ_CNT) return;
    int r = __ldg(rows + i);
    int pos = g_off[r] + atomicAdd(&g_cnt[r], 1);
    g_pcv[pos] = make_int2(__ldg(cols + i), __float_as_int(__ldg(vals + i)));
}

__global__ void __launch_bounds__(256) gather_kernel(
    const float* __restrict__ news_agg,
    float* __restrict__ user_seg)
{
    int w    = (blockIdx.x * 256 + threadIdx.x) >> 5;
    int lane = threadIdx.x & 31;
    if (w >= N_USERS) return;
    int j = g_off[w], e = g_off[w + 1];
    float2 acc = make_float2(0.f, 0.f);
    for (; j + 4 <= e; j += 4) {
        int2 c0 = g_pcv[j], c1 = g_pcv[j+1], c2 = g_pcv[j+2], c3 = g_pcv[j+3];
        float2 a = *(const float2*)(news_agg + (size_t)c0.x * DIM + 2 * lane);
        float2 b = *(const float2*)(news_agg + (size_t)c1.x * DIM + 2 * lane);
        float2 c = *(const float2*)(news_agg + (size_t)c2.x * DIM + 2 * lane);
        float2 d = *(const float2*)(news_agg + (size_t)c3.x * DIM + 2 * lane);
        float v0 = __int_as_float(c0.y), v1 = __int_as_float(c1.y);
        float v2 = __int_as_float(c2.y), v3 = __int_as_float(c3.y);
        acc.x += v0*a.x + v1*b.x + v2*c.x + v3*d.x;
        acc.y += v0*a.y + v1*b.y + v2*c.y + v3*d.y;
    }
    for (; j < e; j++) {
        int2 cv = g_pcv[j];
        float2 a = *(const float2*)(news_agg + (size_t)cv.x * DIM + 2 * lane);
        float v = __int_as_float(cv.y);
        acc.x += v * a.x;
        acc.y += v * a.y;
    }
    *(float2*)(user_seg + (size_t)w * DIM + 2 * lane) = acc;
}

__global__ void __launch_bounds__(256) combine_kernel(float* __restrict__ user_out)
{
    int w    = (blockIdx.x * blockDim.x + threadIdx.x) >> 5;
    int lane = threadIdx.x & 31;
    if (w >= N_USERS) return;
    int qt = w >> 7, r = w & 127;

    float M = -CUDART_INF_F;
    float ms[KSPL], ls[KSPL];
    #pragma unroll
    for (int s = 0; s < KSPL; s++) {
        size_t u = (size_t)(qt * KSPL + s);
        ms[s] = g_pm[u * 128 + r];
        ls[s] = g_pl[u * 128 + r];
        M = fmaxf(M, ms[s]);
    }
    float L = 0.f, ax = 0.f, ay = 0.f;
    #pragma unroll
    for (int s = 0; s < KSPL; s++) {
        size_t u = (size_t)(qt * KSPL + s);
        float e = exp2f(ms[s] - M);
        L += e * ls[s];
        float2 o2 = ((const float2*)(g_po + (u * 128 + r) * 64))[lane];
        ax += e * o2.x;
        ay += e * o2.y;
    }
    float inv = 1.f / L;
    float2* up = (float2*)(user_out + (size_t)w * DIM);
    float2 sg = up[lane];
    up[lane] = make_float2(sg.x + ax * inv * sg.x,
                           sg.y + ay * inv * sg.y);
}

// ---------------------------------------------------------------------------
// Launch: R11 3-stream fork (s2 equal priority).
// ---------------------------------------------------------------------------
extern "C" void kernel_launch(void* const* d_in, const int* in_sizes, int n_in,
                              void* d_out, int out_size)
{
    const float* user_emb = (const float*)d_in[0];
    const float* news_emb = (const float*)d_in[1];
    const float* ent_emb  = (const float*)d_in[2];
    const float* rel_emb  = (const float*)d_in[3];
    const int*   news_ent = (const int*)d_in[4];
    const int*   news_rel = (const int*)d_in[5];
    const int*   nb_ent   = (const int*)d_in[6];
    const int*   nb_rel   = (const int*)d_in[7];
    const int*   irows    = (const int*)d_in[8];
    const int*   icols    = (const int*)d_in[9];
    const float* ivals    = (const float*)d_in[10];

    float* out      = (float*)d_out;
    float* news_out = out;
    float* ent_out  = out + (size_t)N_NEWS * DIM;
    float* user_out = ent_out + (size_t)N_ENT * DIM;

    static cudaStream_t s0 = nullptr, s1 = nullptr, s2 = nullptr;
    static cudaEvent_t  ev0, evNews, evG, evE, evDone;
    if (!s0) {
        int lo, hi;
        cudaDeviceGetStreamPriorityRange(&lo, &hi);
        cudaStreamCreateWithPriority(&s0, cudaStreamNonBlocking, hi);
        cudaStreamCreateWithPriority(&s1, cudaStreamNonBlocking, lo);
        cudaStreamCreateWithPriority(&s2, cudaStreamNonBlocking, hi);
        cudaEventCreateWithFlags(&ev0,    cudaEventDisableTiming);
        cudaEventCreateWithFlags(&evNews, cudaEventDisableTiming);
        cudaEventCreateWithFlags(&evG,    cudaEventDisableTiming);
        cudaEventCreateWithFlags(&evE,    cudaEventDisableTiming);
        cudaEventCreateWithFlags(&evDone, cudaEventDisableTiming);
        cudaFuncSetAttribute(attn_mma_kernel,
                             cudaFuncAttributeMaxDynamicSharedMemorySize, SMEM_ATT);
    }

    void* cnt_ptr = nullptr;
    cudaGetSymbolAddress(&cnt_ptr, g_cnt);

    cudaEventRecord(ev0, 0);
    cudaStreamWaitEvent(s0, ev0, 0);
    cudaStreamWaitEvent(s1, ev0, 0);
    cudaStreamWaitEvent(s2, ev0, 0);

    // s0 (high prio): news agg -> attn
    agg16_kernel<true><<<(KVROWS + 15) / 16, 256, 0, s0>>>(
        news_emb, ent_emb, rel_emb, news_ent, news_rel,
        news_out, N_NEWS, KVROWS);
    cudaEventRecord(evNews, s0);
    attn_mma_kernel<<<ATT_UNITS, 256, SMEM_ATT, s0>>>(user_emb);

    // s2 (equal prio): entity agg
    agg16_kernel<false><<<(N_ENT + 15) / 16, 256, 0, s2>>>(
        ent_emb, ent_emb, rel_emb, nb_ent, nb_rel,
        ent_out, N_ENT, N_ENT);
    cudaEventRecord(evE, s2);

    // s1 (low prio): CSR build, then gather after news agg
    cudaMemsetAsync(cnt_ptr, 0, N_USERS * sizeof(int), s1);
    hist_kernel<<<(NNZ_CNT + 255) / 256, 256, 0, s1>>>(irows);
    scan_kernel<<<1, 1024, 0, s1>>>();
    cudaMemsetAsync(cnt_ptr, 0, N_USERS * sizeof(int), s1);
    scatter_kernel<<<(NNZ_CNT + 255) / 256, 256, 0, s1>>>(irows, icols, ivals);
    cudaStreamWaitEvent(s1, evNews, 0);
    gather_kernel<<<(N_USERS * 32 + 255) / 256, 256, 0, s1>>>(news_out, user_out);
    cudaEventRecord(evG, s1);

    // s0: join gather, run combine
    cudaStreamWaitEvent(s0, evG, 0);
    combine_kernel<<<(N_USERS + 7) / 8, 256, 0, s0>>>(user_out);
    cudaEventRecord(evDone, s0);

    cudaStreamWaitEvent(0, evDone, 0);
    cudaStreamWaitEvent(0, evE, 0);
}

// round 14
// speedup vs baseline: 1.3021x; 1.0068x over previous
#include <cuda_runtime.h>
#include <cuda_fp16.h>
#include <math_constants.h>
#include <cstdint>
#include <cstddef>

#define N_USERS 10000
#define N_NEWS  10000
#define N_ENT   100000
#define N_RELS  32
#define DIM     64
#define KNB     20
#define NNZ_CNT 500000
#define LOG2E_F 1.44269504088896340736f

// -------------------- attention (mma.sync fp16) config ---------------------
#define QTILE   128
#define KTILE   64
#define QTILES  79                  // ceil(10000/128)
#define NKT     157                 // ceil(10000/64)
#define KVROWS  (NKT * KTILE)       // 10048 (48 zero-pad rows)
#define KSPL    15
#define ATT_UNITS (QTILES * KSPL)   // 1185

__device__ float g_po[(size_t)ATT_UNITS * 128 * 64];
__device__ float g_pl[(size_t)ATT_UNITS * 128];
__device__ float g_pm[(size_t)ATT_UNITS * 128];

// pre-split KV in fp16 (hi only; 2-term S split keeps Q_lo x K_hi)
__device__ __half g_kvhi[(size_t)KVROWS * DIM];

// CSR scratch for the user segment-sum
__device__ int  g_cnt[N_USERS];
__device__ int  g_off[N_USERS + 1];
__device__ int2 g_pcv[NNZ_CNT];       // (col, val-bits) sorted by row

// smem map (bytes): Q hi/lo 16KB each; 3 K buffers of 8KB (hi only)
#define SQHI  0
#define SQLO  16384
#define SKB(b)   (32768 + (b) * 8192)
#define SMEM_ATT 57344

// ----------------------------- helpers -------------------------------------
__device__ __forceinline__ uint32_t smem_u32(const void* p) {
    uint32_t a;
    asm("{ .reg .u64 t; cvta.to.shared.u64 t, %1; cvt.u32.u64 %0, t; }"
        : "=r"(a) : "l"(p));
    return a;
}
__device__ __forceinline__ void ldsm4(uint32_t r[4], uint32_t addr) {
    asm volatile("ldmatrix.sync.aligned.m8n8.x4.shared.b16 {%0,%1,%2,%3}, [%4];"
        : "=r"(r[0]), "=r"(r[1]), "=r"(r[2]), "=r"(r[3]) : "r"(addr));
}
__device__ __forceinline__ void ldsm4t(uint32_t r[4], uint32_t addr) {
    asm volatile("ldmatrix.sync.aligned.m8n8.x4.trans.shared.b16 {%0,%1,%2,%3}, [%4];"
        : "=r"(r[0]), "=r"(r[1]), "=r"(r[2]), "=r"(r[3]) : "r"(addr));
}
__device__ __forceinline__ void mma16816(float d[4], const uint32_t a[4],
                                         uint32_t b0, uint32_t b1) {
    asm volatile(
        "mma.sync.aligned.m16n8k16.row.col.f32.f16.f16.f32 "
        "{%0,%1,%2,%3}, {%4,%5,%6,%7}, {%8,%9}, {%0,%1,%2,%3};"
        : "+f"(d[0]), "+f"(d[1]), "+f"(d[2]), "+f"(d[3])
        : "r"(a[0]), "r"(a[1]), "r"(a[2]), "r"(a[3]), "r"(b0), "r"(b1));
}
__device__ __forceinline__ uint32_t f2h2(float x, float y) {
    __half2 h = __floats2half2_rn(x, y);
    return *reinterpret_cast<uint32_t*>(&h);
}
__device__ __forceinline__ float2 h22f2(uint32_t u) {
    __half2 h = *reinterpret_cast<__half2*>(&u);
    return __half22float2(h);
}
__device__ __forceinline__ void split_chunk(float4 a, float4 b,
                                            uint4& hi, uint4& lo) {
    hi = make_uint4(f2h2(a.x, a.y), f2h2(a.z, a.w), f2h2(b.x, b.y), f2h2(b.z, b.w));
    float2 r0 = h22f2(hi.x), r1 = h22f2(hi.y), r2 = h22f2(hi.z), r3 = h22f2(hi.w);
    lo = make_uint4(f2h2(a.x - r0.x, a.y - r0.y), f2h2(a.z - r1.x, a.w - r1.y),
                    f2h2(b.x - r2.x, b.y - r2.y), f2h2(b.z - r3.x, b.w - r3.y));
}
__device__ __forceinline__ uint32_t swadr(uint32_t base, uint32_t row, uint32_t chunk) {
    return base + row * 128u + ((chunk ^ (row & 7u)) << 4);
}
__device__ __forceinline__ void cp16(uint32_t dst, const void* src) {
    asm volatile("cp.async.ca.shared.global [%0], [%1], 16;"
                 :: "r"(dst), "l"(src) : "memory");
}
#define CP_COMMIT() asm volatile("cp.async.commit_group;" ::: "memory")
#define CP_WAIT(n)  asm volatile("cp.async.wait_group %0;" :: "n"(n) : "memory")

// ---------------------------------------------------------------------------
// FA2 on mma.sync fp16 (R13, unchanged): 2-term S split; O = P @ V_hi.
// ---------------------------------------------------------------------------
__global__ void __launch_bounds__(256, 2)
attn_mma_kernel(const float* __restrict__ Q)
{
    extern __shared__ char smraw[];
    const uint32_t sb = smem_u32(smraw);
    const int tid  = threadIdx.x;
    const int wrp  = tid >> 5;
    const int lane = tid & 31;
    const int qt   = blockIdx.x / KSPL;
    const int ks   = blockIdx.x % KSPL;
    const int nt   = (NKT - ks + KSPL - 1) / KSPL;

    // ---- stage Q (2 threads per row), scaled by log2e, hi/lo fp16 ----
    {
        int r = tid >> 1, hc = tid & 1;
        int gr = qt * QTILE + r;
        const float4* src = (const float4*)(Q + (size_t)gr * DIM) + hc * 8;
        #pragma unroll
        for (int i = 0; i < 4; i++) {
            float4 a, b;
            if (gr < N_USERS) { a = src[2 * i]; b = src[2 * i + 1]; }
            else { a = make_float4(0.f, 0.f, 0.f, 0.f); b = a; }
            a.x *= LOG2E_F; a.y *= LOG2E_F; a.z *= LOG2E_F; a.w *= LOG2E_F;
            b.x *= LOG2E_F; b.y *= LOG2E_F; b.z *= LOG2E_F; b.w *= LOG2E_F;
            uint4 hi, lo;
            split_chunk(a, b, hi, lo);
            uint32_t c = hc * 4 + i;
            *(uint4*)(smraw + SQHI + swadr(0, r, c)) = hi;
            *(uint4*)(smraw + SQLO + swadr(0, r, c)) = lo;
        }
    }

    // ---- prologue: prefetch tiles 0 and 1 (4 threads per key row) ----
    const int pr = tid >> 2, pq = tid & 3;
    #pragma unroll
    for (int pt = 0; pt < 2; pt++) {
        size_t key = (size_t)(ks + KSPL * pt) * KTILE + pr;
        const char* ghi = (const char*)g_kvhi + key * 128;
        #pragma unroll
        for (int i = 0; i < 2; i++) {
            uint32_t c = pq * 2 + i;
            cp16(sb + SKB(pt) + swadr(0, pr, c), ghi + c * 16);
        }
        CP_COMMIT();
    }
    __syncthreads();     // Q stores visible

    // ---- Q fragments ----
    uint32_t qh[4][4], ql[4][4];
    #pragma unroll
    for (int kp = 0; kp < 4; kp++) {
        uint32_t row = 16 * wrp + ((lane >> 3) & 1) * 8 + (lane & 7);
        uint32_t ch  = 2 * kp + ((lane >> 4) & 1);
        ldsm4(qh[kp], swadr(sb + SQHI, row, ch));
        ldsm4(ql[kp], swadr(sb + SQLO, row, ch));
    }

    float o[8][4];
    float m[2], l[2];
    #pragma unroll
    for (int n = 0; n < 8; n++)
        #pragma unroll
        for (int k = 0; k < 4; k++) o[n][k] = 0.f;
    m[0] = m[1] = -CUDART_INF_F;
    l[0] = l[1] = 0.f;

    for (int t = 0; t < nt; t++) {
        const int kbase = (ks + KSPL * t) * KTILE;

        CP_WAIT(1);
        __syncthreads();

        if (t + 2 < nt) {
            size_t key = (size_t)(ks + KSPL * (t + 2)) * KTILE + pr;
            const char* ghi = (const char*)g_kvhi + key * 128;
            uint32_t bb = SKB((t + 2) % 3);
            #pragma unroll
            for (int i = 0; i < 2; i++) {
                uint32_t c = pq * 2 + i;
                cp16(sb + bb + swadr(0, pr, c), ghi + c * 16);
            }
        }
        CP_COMMIT();

        const uint32_t khi = sb + SKB(t % 3);

        // ---- S = Q @ K^T (2-term split) ----
        float s[8][4];
        #pragma unroll
        for (int n = 0; n < 8; n++)
            #pragma unroll
            for (int k = 0; k < 4; k++) s[n][k] = 0.f;

        #pragma unroll
        for (int kp = 0; kp < 4; kp++) {
            #pragma unroll
            for (int p = 0; p < 4; p++) {
                uint32_t key = 16u * p + ((lane >> 4) & 1) * 8 + (lane & 7);
                uint32_t ch  = 2u * kp + ((lane >> 3) & 1);
                uint32_t bh[4];
                ldsm4(bh, swadr(khi, key, ch));
                mma16816(s[2*p],   qh[kp], bh[0], bh[1]);
                mma16816(s[2*p],   ql[kp], bh[0], bh[1]);
                mma16816(s[2*p+1], qh[kp], bh[2], bh[3]);
                mma16816(s[2*p+1], ql[kp], bh[2], bh[3]);
            }
        }

        // ---- mask tail keys ----
        if (kbase + KTILE > N_NEWS) {
            #pragma unroll
            for (int n = 0; n < 8; n++) {
                int c0 = kbase + 8 * n + (lane & 3) * 2;
                #pragma unroll
                for (int d = 0; d < 2; d++) {
                    if (c0 + d >= N_NEWS) {
                        s[n][d]     = -CUDART_INF_F;
                        s[n][d + 2] = -CUDART_INF_F;
                    }
                }
            }
        }

        // ---- online softmax (log2 domain) ----
        #pragma unroll
        for (int h = 0; h < 2; h++) {
            float mx = -CUDART_INF_F;
            #pragma unroll
            for (int n = 0; n < 8; n++)
                mx = fmaxf(mx, fmaxf(s[n][2*h], s[n][2*h+1]));
            mx = fmaxf(mx, __shfl_xor_sync(0xffffffffu, mx, 1));
            mx = fmaxf(mx, __shfl_xor_sync(0xffffffffu, mx, 2));
            if (mx > m[h]) {
                float sc = exp2f(m[h] - mx);
                m[h] = mx;
                l[h] *= sc;
                #pragma unroll
                for (int n = 0; n < 8; n++) {
                    o[n][2*h]   *= sc;
                    o[n][2*h+1] *= sc;
                }
            }
            #pragma unroll
            for (int n = 0; n < 8; n++) {
                float e0 = exp2f(s[n][2*h]   - m[h]);
                float e1 = exp2f(s[n][2*h+1] - m[h]);
                uint32_t u = f2h2(e0, e1);
                float2 er = h22f2(u);
                s[n][2*h]   = er.x;
                s[n][2*h+1] = er.y;
                l[h] += er.x + er.y;
            }
        }

        // ---- O += P @ V_hi ----
        #pragma unroll
        for (int kk = 0; kk < 4; kk++) {
            uint32_t pa[4];
            pa[0] = f2h2(s[2*kk][0],   s[2*kk][1]);
            pa[1] = f2h2(s[2*kk][2],   s[2*kk][3]);
            pa[2] = f2h2(s[2*kk+1][0], s[2*kk+1][1]);
            pa[3] = f2h2(s[2*kk+1][2], s[2*kk+1][3]);
            #pragma unroll
            for (int p = 0; p < 4; p++) {
                uint32_t key = 16u * kk + ((lane >> 3) & 1) * 8 + (lane & 7);
                uint32_t ch  = 2u * p + ((lane >> 4) & 1);
                uint32_t vh[4];
                ldsm4t(vh, swadr(khi, key, ch));
                mma16816(o[2*p],   pa, vh[0], vh[1]);
                mma16816(o[2*p+1], pa, vh[2], vh[3]);
            }
        }
    }

    // ---- reduce l across the 4 lanes of each row ----
    #pragma unroll
    for (int h = 0; h < 2; h++) {
        l[h] += __shfl_xor_sync(0xffffffffu, l[h], 1);
        l[h] += __shfl_xor_sync(0xffffffffu, l[h], 2);
    }

    // ---- write partial ----
    const int g = lane >> 2;
    #pragma unroll
    for (int h = 0; h < 2; h++) {
        int row = 16 * wrp + 8 * h + g;
        float* pb = g_po + ((size_t)blockIdx.x * 128 + row) * 64;
        #pragma unroll
        for (int n = 0; n < 8; n++) {
            int c = 8 * n + (lane & 3) * 2;
            *(float2*)(pb + c) = make_float2(o[n][2*h], o[n][2*h+1]);
        }
        if ((lane & 3) == 0) {
            g_pm[(size_t)blockIdx.x * 128 + row] = m[h];
            g_pl[(size_t)blockIdx.x * 128 + row] = l[h];
        }
    }
}

// ---------------------------------------------------------------------------
// Aggregation v5: chunked softmax. 4 neighbors per chunk held in registers:
// batched gathers (1 L2 round-trip per chunk), 4 independent shfl trees,
// one rescale per chunk. Single gather per neighbor (R10's flaw avoided).
// ---------------------------------------------------------------------------
template<bool WRITE_KV>
__global__ void __launch_bounds__(256, 4) agg16_kernel(
    const float* __restrict__ head,
    const float* __restrict__ ent,
    const float* __restrict__ rel,
    const int*   __restrict__ nbe,
    const int*   __restrict__ nbr,
    float* __restrict__ out, int N, int Ntotal)
{
    __shared__ float relS[N_RELS * DIM];
    __shared__ int   eS[16 * KNB];
    __shared__ int   rS[16 * KNB];

    const int tid = threadIdx.x;
    for (int i = tid; i < N_RELS * DIM / 4; i += 256)
        ((float4*)relS)[i] = ((const float4*)rel)[i];
    const int rowbase = blockIdx.x * 16;
    for (int i = tid; i < 16 * KNB; i += 256) {
        int rr = rowbase + i / KNB;
        bool ok = rr < N;
        eS[i] = ok ? __ldg(nbe + (size_t)rr * KNB + i % KNB) : 0;
        rS[i] = ok ? __ldg(nbr + (size_t)rr * KNB + i % KNB) : 0;
    }
    __syncthreads();

    const int wrp  = tid >> 5;
    const int lane = tid & 31;
    const int rloc = wrp * 2 + (lane >> 4);
    const int sl   = lane & 15;
    const int w    = rowbase + rloc;
    if (w >= Ntotal) return;

    float4 v = make_float4(0.f, 0.f, 0.f, 0.f);

    if (w < N) {
        const float4 h = ((const float4*)(head + (size_t)w * DIM))[sl];
        const int* re = eS + rloc * KNB;
        const int* rr = rS + rloc * KNB;

        float4 sx = make_float4(0.f, 0.f, 0.f, 0.f);
        #pragma unroll 4
        for (int k = 0; k < KNB; k++) {
            float4 a = ((const float4*)(relS + rr[k] * DIM))[sl];
            sx.x += a.x * a.x; sx.y += a.y * a.y;
            sx.z += a.z * a.z; sx.w += a.w * a.w;
        }
        float4 hn = make_float4(fabsf(h.x) * sqrtf(sx.x), fabsf(h.y) * sqrtf(sx.y),
                                fabsf(h.z) * sqrtf(sx.z), fabsf(h.w) * sqrtf(sx.w));

        float m = -CUDART_INF_F, l = 0.f;
        float4 acc = make_float4(0.f, 0.f, 0.f, 0.f);

        #pragma unroll 1
        for (int c0 = 0; c0 < KNB; c0 += 4) {
            float4 t[4];
            float  p[4];
            // batched loads + independent dots
            #pragma unroll
            for (int i = 0; i < 4; i++) {
                float4 ra = ((const float4*)(relS + rr[c0 + i] * DIM))[sl];
                t[i] = ((const float4*)(ent + (size_t)re[c0 + i] * DIM))[sl];
                p[i] = t[i].x * ra.x * hn.x + t[i].y * ra.y * hn.y
                     + t[i].z * ra.z * hn.z + t[i].w * ra.w * hn.w;
            }
            // 4 independent shfl trees (pipeline across i)
            #pragma unroll
            for (int i = 0; i < 4; i++) {
                p[i] += __shfl_xor_sync(0xffffffffu, p[i], 1);
                p[i] += __shfl_xor_sync(0xffffffffu, p[i], 2);
                p[i] += __shfl_xor_sync(0xffffffffu, p[i], 4);
                p[i] += __shfl_xor_sync(0xffffffffu, p[i], 8);
                p[i] *= p[i];
            }
            // one rescale per chunk
            float mx = fmaxf(fmaxf(p[0], p[1]), fmaxf(p[2], p[3]));
            if (mx > m) {
                float sc = __expf(m - mx);   // exp(-inf)=0 on first chunk
                l *= sc;
                acc.x *= sc; acc.y *= sc; acc.z *= sc; acc.w *= sc;
                m = mx;
            }
            #pragma unroll
            for (int i = 0; i < 4; i++) {
                float e = __expf(p[i] - m);
                l += e;
                acc.x += e * t[i].x; acc.y += e * t[i].y;
                acc.z += e * t[i].z; acc.w += e * t[i].w;
            }
        }
        float inv = 1.f / l;
        v = make_float4(acc.x * inv, acc.y * inv, acc.z * inv, acc.w * inv);
        ((float4*)(out + (size_t)w * DIM))[sl] = v;
    }

    if (WRITE_KV) {
        uint32_t h0 = f2h2(v.x, v.y), h1 = f2h2(v.z, v.w);
        *(uint2*)((char*)g_kvhi + ((size_t)w * DIM + sl * 4) * 2) = make_uint2(h0, h1);
    }
}

// ---------------------------------------------------------------------------
// CSR build + gather + combine (unchanged).
// ---------------------------------------------------------------------------
__global__ void __launch_bounds__(256) hist_kernel(const int* __restrict__ rows)
{
    int i = blockIdx.x * 256 + threadIdx.x;
    if (i < NNZ_CNT) atomicAdd(&g_cnt[__ldg(rows + i)], 1);
}

__global__ void __launch_bounds__(1024) scan_kernel()
{
    __shared__ int wsum[32];
    __shared__ int carry;
    const int tid = threadIdx.x, lane = tid & 31, wid = tid >> 5;
    if (tid == 0) { carry = 0; g_off[0] = 0; }
    __syncthreads();
    for (int base = 0; base < N_USERS; base += 1024) {
        int i = base + tid;
        int v = (i < N_USERS) ? g_cnt[i] : 0;
        #pragma unroll
        for (int d = 1; d < 32; d <<= 1) {
            int y = __shfl_up_sync(0xffffffffu, v, d);
            if (lane >= d) v += y;
        }
        if (lane == 31) wsum[wid] = v;
        __syncthreads();
        if (wid == 0) {
            int w = wsum[lane];
            #pragma unroll
            for (int d = 1; d < 32; d <<= 1) {
                int y = __shfl_up_sync(0xffffffffu, w, d);
                if (lane >= d) w += y;
            }
            wsum[lane] = w;
        }
        __syncthreads();
        int incl = v + (wid ? wsum[wid - 1] : 0) + carry;
        if (i < N_USERS) g_off[i + 1] = incl;
        __syncthreads();
        if (tid == 1023) carry = incl;
        __syncthreads();
    }
}

__global__ void __launch_bounds__(256) scatter_kernel(
    const int* __restrict__ rows,
    const int* __restrict__ cols,
    const float* __restrict__ vals)
{
    int i = blockIdx.x * 256 + threadIdx.x;
    if (i >= NNZ_CNT) return;
    int r = __ldg(rows + i);
    int pos = g_off[r] + atomicAdd(&g_cnt[r], 1);
    g_pcv[pos] = make_int2(__ldg(cols + i), __float_as_int(__ldg(vals + i)));
}

__global__ void __launch_bounds__(256) gather_kernel(
    const float* __restrict__ news_agg,
    float* __restrict__ user_seg)
{
    int w    = (blockIdx.x * 256 + threadIdx.x) >> 5;
    int lane = threadIdx.x & 31;
    if (w >= N_USERS) return;
    int j = g_off[w], e = g_off[w + 1];
    float2 acc = make_float2(0.f, 0.f);
    for (; j + 4 <= e; j += 4) {
        int2 c0 = g_pcv[j], c1 = g_pcv[j+1], c2 = g_pcv[j+2], c3 = g_pcv[j+3];
        float2 a = *(const float2*)(news_agg + (size_t)c0.x * DIM + 2 * lane);
        float2 b = *(const float2*)(news_agg + (size_t)c1.x * DIM + 2 * lane);
        float2 c = *(const float2*)(news_agg + (size_t)c2.x * DIM + 2 * lane);
        float2 d = *(const float2*)(news_agg + (size_t)c3.x * DIM + 2 * lane);
        float v0 = __int_as_float(c0.y), v1 = __int_as_float(c1.y);
        float v2 = __int_as_float(c2.y), v3 = __int_as_float(c3.y);
        acc.x += v0*a.x + v1*b.x + v2*c.x + v3*d.x;
        acc.y += v0*a.y + v1*b.y + v2*c.y + v3*d.y;
    }
    for (; j < e; j++) {
        int2 cv = g_pcv[j];
        float2 a = *(const float2*)(news_agg + (size_t)cv.x * DIM + 2 * lane);
        float v = __int_as_float(cv.y);
        acc.x += v * a.x;
        acc.y += v * a.y;
    }
    *(float2*)(user_seg + (size_t)w * DIM + 2 * lane) = acc;
}

__global__ void __launch_bounds__(256) combine_kernel(float* __restrict__ user_out)
{
    int w    = (blockIdx.x * blockDim.x + threadIdx.x) >> 5;
    int lane = threadIdx.x & 31;
    if (w >= N_USERS) return;
    int qt = w >> 7, r = w & 127;

    float M = -CUDART_INF_F;
    float ms[KSPL], ls[KSPL];
    #pragma unroll
    for (int s = 0; s < KSPL; s++) {
        size_t u = (size_t)(qt * KSPL + s);
        ms[s] = g_pm[u * 128 + r];
        ls[s] = g_pl[u * 128 + r];
        M = fmaxf(M, ms[s]);
    }
    float L = 0.f, ax = 0.f, ay = 0.f;
    #pragma unroll
    for (int s = 0; s < KSPL; s++) {
        size_t u = (size_t)(qt * KSPL + s);
        float e = exp2f(ms[s] - M);
        L += e * ls[s];
        float2 o2 = ((const float2*)(g_po + (u * 128 + r) * 64))[lane];
        ax += e * o2.x;
        ay += e * o2.y;
    }
    float inv = 1.f / L;
    float2* up = (float2*)(user_out + (size_t)w * DIM);
    float2 sg = up[lane];
    up[lane] = make_float2(sg.x + ax * inv * sg.x,
                           sg.y + ay * inv * sg.y);
}

// ---------------------------------------------------------------------------
// Launch: R11/R13 3-stream fork (s2 equal priority).
// ---------------------------------------------------------------------------
extern "C" void kernel_launch(void* const* d_in, const int* in_sizes, int n_in,
                              void* d_out, int out_size)
{
    const float* user_emb = (const float*)d_in[0];
    const float* news_emb = (const float*)d_in[1];
    const float* ent_emb  = (const float*)d_in[2];
    const float* rel_emb  = (const float*)d_in[3];
    const int*   news_ent = (const int*)d_in[4];
    const int*   news_rel = (const int*)d_in[5];
    const int*   nb_ent   = (const int*)d_in[6];
    const int*   nb_rel   = (const int*)d_in[7];
    const int*   irows    = (const int*)d_in[8];
    const int*   icols    = (const int*)d_in[9];
    const float* ivals    = (const float*)d_in[10];

    float* out      = (float*)d_out;
    float* news_out = out;
    float* ent_out  = out + (size_t)N_NEWS * DIM;
    float* user_out = ent_out + (size_t)N_ENT * DIM;

    static cudaStream_t s0 = nullptr, s1 = nullptr, s2 = nullptr;
    static cudaEvent_t  ev0, evNews, evG, evE, evDone;
    if (!s0) {
        int lo, hi;
        cudaDeviceGetStreamPriorityRange(&lo, &hi);
        cudaStreamCreateWithPriority(&s0, cudaStreamNonBlocking, hi);
        cudaStreamCreateWithPriority(&s1, cudaStreamNonBlocking, lo);
        cudaStreamCreateWithPriority(&s2, cudaStreamNonBlocking, hi);
        cudaEventCreateWithFlags(&ev0,    cudaEventDisableTiming);
        cudaEventCreateWithFlags(&evNews, cudaEventDisableTiming);
        cudaEventCreateWithFlags(&evG,    cudaEventDisableTiming);
        cudaEventCreateWithFlags(&evE,    cudaEventDisableTiming);
        cudaEventCreateWithFlags(&evDone, cudaEventDisableTiming);
        cudaFuncSetAttribute(attn_mma_kernel,
                             cudaFuncAttributeMaxDynamicSharedMemorySize, SMEM_ATT);
    }

    void* cnt_ptr = nullptr;
    cudaGetSymbolAddress(&cnt_ptr, g_cnt);

    cudaEventRecord(ev0, 0);
    cudaStreamWaitEvent(s0, ev0, 0);
    cudaStreamWaitEvent(s1, ev0, 0);
    cudaStreamWaitEvent(s2, ev0, 0);

    // s0 (high prio): news agg -> attn
    agg16_kernel<true><<<(KVROWS + 15) / 16, 256, 0, s0>>>(
        news_emb, ent_emb, rel_emb, news_ent, news_rel,
        news_out, N_NEWS, KVROWS);
    cudaEventRecord(evNews, s0);
    attn_mma_kernel<<<ATT_UNITS, 256, SMEM_ATT, s0>>>(user_emb);

    // s2 (equal prio): entity agg
    agg16_kernel<false><<<(N_ENT + 15) / 16, 256, 0, s2>>>(
        ent_emb, ent_emb, rel_emb, nb_ent, nb_rel,
        ent_out, N_ENT, N_ENT);
    cudaEventRecord(evE, s2);

    // s1 (low prio): CSR build, then gather after news agg
    cudaMemsetAsync(cnt_ptr, 0, N_USERS * sizeof(int), s1);
    hist_kernel<<<(NNZ_CNT + 255) / 256, 256, 0, s1>>>(irows);
    scan_kernel<<<1, 1024, 0, s1>>>();
    cudaMemsetAsync(cnt_ptr, 0, N_USERS * sizeof(int), s1);
    scatter_kernel<<<(NNZ_CNT + 255) / 256, 256, 0, s1>>>(irows, icols, ivals);
    cudaStreamWaitEvent(s1, evNews, 0);
    gather_kernel<<<(N_USERS * 32 + 255) / 256, 256, 0, s1>>>(news_out, user_out);
    cudaEventRecord(evG, s1);

    // s0: join gather, run combine
    cudaStreamWaitEvent(s0, evG, 0);
    combine_kernel<<<(N_USERS + 7) / 8, 256, 0, s0>>>(user_out);
    cudaEventRecord(evDone, s0);

    cudaStreamWaitEvent(0, evDone, 0);
    cudaStreamWaitEvent(0, evE, 0);
}

// round 16
// speedup vs baseline: 1.3131x; 1.0084x over previous
#include <cuda_runtime.h>
#include <cuda_fp16.h>
#include <math_constants.h>
#include <cstdint>
#include <cstddef>

#define N_USERS 10000
#define N_NEWS  10000
#define N_ENT   100000
#define N_RELS  32
#define DIM     64
#define KNB     20
#define NNZ_CNT 500000
#define LOG2E_F 1.44269504088896340736f

// -------------------- attention (mma.sync fp16) config ---------------------
#define QTILE   128
#define KTILE   64
#define QTILES  79                  // ceil(10000/128)
#define NKT     157                 // ceil(10000/64)
#define KVROWS  (NKT * KTILE)       // 10048 (48 zero-pad rows)
#define KSPL    15
#define ATT_UNITS (QTILES * KSPL)   // 1185

__device__ float g_po[(size_t)ATT_UNITS * 128 * 64];
__device__ float g_pl[(size_t)ATT_UNITS * 128];
__device__ float g_pm[(size_t)ATT_UNITS * 128];

// pre-split KV in fp16 (hi only; 2-term S split keeps Q_lo x K_hi)
__device__ __half g_kvhi[(size_t)KVROWS * DIM];

// CSR scratch for the user segment-sum
__device__ int  g_cnt[N_USERS];
__device__ int  g_off[N_USERS + 1];
__device__ int2 g_pcv[NNZ_CNT];       // (col, val-bits) sorted by row

// smem map (bytes): Q hi/lo 16KB each; 3 K buffers of 8KB (hi only)
#define SQHI  0
#define SQLO  16384
#define SKB(b)   (32768 + (b) * 8192)
#define SMEM_ATT 57344

// ----------------------------- helpers -------------------------------------
__device__ __forceinline__ uint32_t smem_u32(const void* p) {
    uint32_t a;
    asm("{ .reg .u64 t; cvta.to.shared.u64 t, %1; cvt.u32.u64 %0, t; }"
        : "=r"(a) : "l"(p));
    return a;
}
__device__ __forceinline__ void ldsm4(uint32_t r[4], uint32_t addr) {
    asm volatile("ldmatrix.sync.aligned.m8n8.x4.shared.b16 {%0,%1,%2,%3}, [%4];"
        : "=r"(r[0]), "=r"(r[1]), "=r"(r[2]), "=r"(r[3]) : "r"(addr));
}
__device__ __forceinline__ void ldsm4t(uint32_t r[4], uint32_t addr) {
    asm volatile("ldmatrix.sync.aligned.m8n8.x4.trans.shared.b16 {%0,%1,%2,%3}, [%4];"
        : "=r"(r[0]), "=r"(r[1]), "=r"(r[2]), "=r"(r[3]) : "r"(addr));
}
__device__ __forceinline__ void mma16816(float d[4], const uint32_t a[4],
                                         uint32_t b0, uint32_t b1) {
    asm volatile(
        "mma.sync.aligned.m16n8k16.row.col.f32.f16.f16.f32 "
        "{%0,%1,%2,%3}, {%4,%5,%6,%7}, {%8,%9}, {%0,%1,%2,%3};"
        : "+f"(d[0]), "+f"(d[1]), "+f"(d[2]), "+f"(d[3])
        : "r"(a[0]), "r"(a[1]), "r"(a[2]), "r"(a[3]), "r"(b0), "r"(b1));
}
__device__ __forceinline__ uint32_t f2h2(float x, float y) {
    __half2 h = __floats2half2_rn(x, y);
    return *reinterpret_cast<uint32_t*>(&h);
}
__device__ __forceinline__ float2 h22f2(uint32_t u) {
    __half2 h = *reinterpret_cast<__half2*>(&u);
    return __half22float2(h);
}
__device__ __forceinline__ void split_chunk(float4 a, float4 b,
                                            uint4& hi, uint4& lo) {
    hi = make_uint4(f2h2(a.x, a.y), f2h2(a.z, a.w), f2h2(b.x, b.y), f2h2(b.z, b.w));
    float2 r0 = h22f2(hi.x), r1 = h22f2(hi.y), r2 = h22f2(hi.z), r3 = h22f2(hi.w);
    lo = make_uint4(f2h2(a.x - r0.x, a.y - r0.y), f2h2(a.z - r1.x, a.w - r1.y),
                    f2h2(b.x - r2.x, b.y - r2.y), f2h2(b.z - r3.x, b.w - r3.y));
}
__device__ __forceinline__ uint32_t swadr(uint32_t base, uint32_t row, uint32_t chunk) {
    return base + row * 128u + ((chunk ^ (row & 7u)) << 4);
}
__device__ __forceinline__ void cp16(uint32_t dst, const void* src) {
    asm volatile("cp.async.ca.shared.global [%0], [%1], 16;"
                 :: "r"(dst), "l"(src) : "memory");
}
#define CP_COMMIT() asm volatile("cp.async.commit_group;" ::: "memory")
#define CP_WAIT(n)  asm volatile("cp.async.wait_group %0;" :: "n"(n) : "memory")

// ---------------------------------------------------------------------------
// FA2 on mma.sync fp16 (R13/R14, unchanged): 2-term S split; O = P @ V_hi.
// ---------------------------------------------------------------------------
__global__ void __launch_bounds__(256, 2)
attn_mma_kernel(const float* __restrict__ Q)
{
    extern __shared__ char smraw[];
    const uint32_t sb = smem_u32(smraw);
    const int tid  = threadIdx.x;
    const int wrp  = tid >> 5;
    const int lane = tid & 31;
    const int qt   = blockIdx.x / KSPL;
    const int ks   = blockIdx.x % KSPL;
    const int nt   = (NKT - ks + KSPL - 1) / KSPL;

    // ---- stage Q (2 threads per row), scaled by log2e, hi/lo fp16 ----
    {
        int r = tid >> 1, hc = tid & 1;
        int gr = qt * QTILE + r;
        const float4* src = (const float4*)(Q + (size_t)gr * DIM) + hc * 8;
        #pragma unroll
        for (int i = 0; i < 4; i++) {
            float4 a, b;
            if (gr < N_USERS) { a = src[2 * i]; b = src[2 * i + 1]; }
            else { a = make_float4(0.f, 0.f, 0.f, 0.f); b = a; }
            a.x *= LOG2E_F; a.y *= LOG2E_F; a.z *= LOG2E_F; a.w *= LOG2E_F;
            b.x *= LOG2E_F; b.y *= LOG2E_F; b.z *= LOG2E_F; b.w *= LOG2E_F;
            uint4 hi, lo;
            split_chunk(a, b, hi, lo);
            uint32_t c = hc * 4 + i;
            *(uint4*)(smraw + SQHI + swadr(0, r, c)) = hi;
            *(uint4*)(smraw + SQLO + swadr(0, r, c)) = lo;
        }
    }

    // ---- prologue: prefetch tiles 0 and 1 (4 threads per key row) ----
    const int pr = tid >> 2, pq = tid & 3;
    #pragma unroll
    for (int pt = 0; pt < 2; pt++) {
        size_t key = (size_t)(ks + KSPL * pt) * KTILE + pr;
        const char* ghi = (const char*)g_kvhi + key * 128;
        #pragma unroll
        for (int i = 0; i < 2; i++) {
            uint32_t c = pq * 2 + i;
            cp16(sb + SKB(pt) + swadr(0, pr, c), ghi + c * 16);
        }
        CP_COMMIT();
    }
    __syncthreads();     // Q stores visible

    // ---- Q fragments ----
    uint32_t qh[4][4], ql[4][4];
    #pragma unroll
    for (int kp = 0; kp < 4; kp++) {
        uint32_t row = 16 * wrp + ((lane >> 3) & 1) * 8 + (lane & 7);
        uint32_t ch  = 2 * kp + ((lane >> 4) & 1);
        ldsm4(qh[kp], swadr(sb + SQHI, row, ch));
        ldsm4(ql[kp], swadr(sb + SQLO, row, ch));
    }

    float o[8][4];
    float m[2], l[2];
    #pragma unroll
    for (int n = 0; n < 8; n++)
        #pragma unroll
        for (int k = 0; k < 4; k++) o[n][k] = 0.f;
    m[0] = m[1] = -CUDART_INF_F;
    l[0] = l[1] = 0.f;

    for (int t = 0; t < nt; t++) {
        const int kbase = (ks + KSPL * t) * KTILE;

        CP_WAIT(1);
        __syncthreads();

        if (t + 2 < nt) {
            size_t key = (size_t)(ks + KSPL * (t + 2)) * KTILE + pr;
            const char* ghi = (const char*)g_kvhi + key * 128;
            uint32_t bb = SKB((t + 2) % 3);
            #pragma unroll
            for (int i = 0; i < 2; i++) {
                uint32_t c = pq * 2 + i;
                cp16(sb + bb + swadr(0, pr, c), ghi + c * 16);
            }
        }
        CP_COMMIT();

        const uint32_t khi = sb + SKB(t % 3);

        // ---- S = Q @ K^T (2-term split) ----
        float s[8][4];
        #pragma unroll
        for (int n = 0; n < 8; n++)
            #pragma unroll
            for (int k = 0; k < 4; k++) s[n][k] = 0.f;

        #pragma unroll
        for (int kp = 0; kp < 4; kp++) {
            #pragma unroll
            for (int p = 0; p < 4; p++) {
                uint32_t key = 16u * p + ((lane >> 4) & 1) * 8 + (lane & 7);
                uint32_t ch  = 2u * kp + ((lane >> 3) & 1);
                uint32_t bh[4];
                ldsm4(bh, swadr(khi, key, ch));
                mma16816(s[2*p],   qh[kp], bh[0], bh[1]);
                mma16816(s[2*p],   ql[kp], bh[0], bh[1]);
                mma16816(s[2*p+1], qh[kp], bh[2], bh[3]);
                mma16816(s[2*p+1], ql[kp], bh[2], bh[3]);
            }
        }

        // ---- mask tail keys ----
        if (kbase + KTILE > N_NEWS) {
            #pragma unroll
            for (int n = 0; n < 8; n++) {
                int c0 = kbase + 8 * n + (lane & 3) * 2;
                #pragma unroll
                for (int d = 0; d < 2; d++) {
                    if (c0 + d >= N_NEWS) {
                        s[n][d]     = -CUDART_INF_F;
                        s[n][d + 2] = -CUDART_INF_F;
                    }
                }
            }
        }

        // ---- online softmax (log2 domain) ----
        #pragma unroll
        for (int h = 0; h < 2; h++) {
            float mx = -CUDART_INF_F;
            #pragma unroll
            for (int n = 0; n < 8; n++)
                mx = fmaxf(mx, fmaxf(s[n][2*h], s[n][2*h+1]));
            mx = fmaxf(mx, __shfl_xor_sync(0xffffffffu, mx, 1));
            mx = fmaxf(mx, __shfl_xor_sync(0xffffffffu, mx, 2));
            if (mx > m[h]) {
                float sc = exp2f(m[h] - mx);
                m[h] = mx;
                l[h] *= sc;
                #pragma unroll
                for (int n = 0; n < 8; n++) {
                    o[n][2*h]   *= sc;
                    o[n][2*h+1] *= sc;
                }
            }
            #pragma unroll
            for (int n = 0; n < 8; n++) {
                float e0 = exp2f(s[n][2*h]   - m[h]);
                float e1 = exp2f(s[n][2*h+1] - m[h]);
                uint32_t u = f2h2(e0, e1);
                float2 er = h22f2(u);
                s[n][2*h]   = er.x;
                s[n][2*h+1] = er.y;
                l[h] += er.x + er.y;
            }
        }

        // ---- O += P @ V_hi ----
        #pragma unroll
        for (int kk = 0; kk < 4; kk++) {
            uint32_t pa[4];
            pa[0] = f2h2(s[2*kk][0],   s[2*kk][1]);
            pa[1] = f2h2(s[2*kk][2],   s[2*kk][3]);
            pa[2] = f2h2(s[2*kk+1][0], s[2*kk+1][1]);
            pa[3] = f2h2(s[2*kk+1][2], s[2*kk+1][3]);
            #pragma unroll
            for (int p = 0; p < 4; p++) {
                uint32_t key = 16u * kk + ((lane >> 3) & 1) * 8 + (lane & 7);
                uint32_t ch  = 2u * p + ((lane >> 4) & 1);
                uint32_t vh[4];
                ldsm4t(vh, swadr(khi, key, ch));
                mma16816(o[2*p],   pa, vh[0], vh[1]);
                mma16816(o[2*p+1], pa, vh[2], vh[3]);
            }
        }
    }

    // ---- reduce l across the 4 lanes of each row ----
    #pragma unroll
    for (int h = 0; h < 2; h++) {
        l[h] += __shfl_xor_sync(0xffffffffu, l[h], 1);
        l[h] += __shfl_xor_sync(0xffffffffu, l[h], 2);
    }

    // ---- write partial ----
    const int g = lane >> 2;
    #pragma unroll
    for (int h = 0; h < 2; h++) {
        int row = 16 * wrp + 8 * h + g;
        float* pb = g_po + ((size_t)blockIdx.x * 128 + row) * 64;
        #pragma unroll
        for (int n = 0; n < 8; n++) {
            int c = 8 * n + (lane & 3) * 2;
            *(float2*)(pb + c) = make_float2(o[n][2*h], o[n][2*h+1]);
        }
        if ((lane & 3) == 0) {
            g_pm[(size_t)blockIdx.x * 128 + row] = m[h];
            g_pl[(size_t)blockIdx.x * 128 + row] = l[h];
        }
    }
}

// ---------------------------------------------------------------------------
// News aggregation (R14: fp32 gathers, chunked softmax, writes KV-hi).
// ---------------------------------------------------------------------------
__global__ void __launch_bounds__(256, 4) news_agg_kernel(
    const float* __restrict__ head,
    const float* __restrict__ ent,
    const float* __restrict__ rel,
    const int*   __restrict__ nbe,
    const int*   __restrict__ nbr,
    float* __restrict__ out)
{
    __shared__ float relS[N_RELS * DIM];
    __shared__ int   eS[16 * KNB];
    __shared__ int   rS[16 * KNB];

    const int tid = threadIdx.x;
    for (int i = tid; i < N_RELS * DIM / 4; i += 256)
        ((float4*)relS)[i] = ((const float4*)rel)[i];
    const int rowbase = blockIdx.x * 16;
    for (int i = tid; i < 16 * KNB; i += 256) {
        int rr = rowbase + i / KNB;
        bool ok = rr < N_NEWS;
        eS[i] = ok ? __ldg(nbe + (size_t)rr * KNB + i % KNB) : 0;
        rS[i] = ok ? __ldg(nbr + (size_t)rr * KNB + i % KNB) : 0;
    }
    __syncthreads();

    const int wrp  = tid >> 5;
    const int lane = tid & 31;
    const int rloc = wrp * 2 + (lane >> 4);
    const int sl   = lane & 15;
    const int w    = rowbase + rloc;
    if (w >= KVROWS) return;

    float4 v = make_float4(0.f, 0.f, 0.f, 0.f);

    if (w < N_NEWS) {
        const float4 h = ((const float4*)(head + (size_t)w * DIM))[sl];
        const int* re = eS + rloc * KNB;
        const int* rr = rS + rloc * KNB;

        float4 sx = make_float4(0.f, 0.f, 0.f, 0.f);
        #pragma unroll 4
        for (int k = 0; k < KNB; k++) {
            float4 a = ((const float4*)(relS + rr[k] * DIM))[sl];
            sx.x += a.x * a.x; sx.y += a.y * a.y;
            sx.z += a.z * a.z; sx.w += a.w * a.w;
        }
        float4 hn = make_float4(fabsf(h.x) * sqrtf(sx.x), fabsf(h.y) * sqrtf(sx.y),
                                fabsf(h.z) * sqrtf(sx.z), fabsf(h.w) * sqrtf(sx.w));

        float m = -CUDART_INF_F, l = 0.f;
        float4 acc = make_float4(0.f, 0.f, 0.f, 0.f);

        #pragma unroll 1
        for (int c0 = 0; c0 < KNB; c0 += 4) {
            float4 t[4];
            float  p[4];
            #pragma unroll
            for (int i = 0; i < 4; i++) {
                float4 ra = ((const float4*)(relS + rr[c0 + i] * DIM))[sl];
                t[i] = ((const float4*)(ent + (size_t)re[c0 + i] * DIM))[sl];
                p[i] = t[i].x * ra.x * hn.x + t[i].y * ra.y * hn.y
                     + t[i].z * ra.z * hn.z + t[i].w * ra.w * hn.w;
            }
            #pragma unroll
            for (int i = 0; i < 4; i++) {
                p[i] += __shfl_xor_sync(0xffffffffu, p[i], 1);
                p[i] += __shfl_xor_sync(0xffffffffu, p[i], 2);
                p[i] += __shfl_xor_sync(0xffffffffu, p[i], 4);
                p[i] += __shfl_xor_sync(0xffffffffu, p[i], 8);
                p[i] *= p[i];
            }
            float mx = fmaxf(fmaxf(p[0], p[1]), fmaxf(p[2], p[3]));
            if (mx > m) {
                float sc = __expf(m - mx);
                l *= sc;
                acc.x *= sc; acc.y *= sc; acc.z *= sc; acc.w *= sc;
                m = mx;
            }
            #pragma unroll
            for (int i = 0; i < 4; i++) {
                float e = __expf(p[i] - m);
                l += e;
                acc.x += e * t[i].x; acc.y += e * t[i].y;
                acc.z += e * t[i].z; acc.w += e * t[i].w;
            }
        }
        float inv = 1.f / l;
        v = make_float4(acc.x * inv, acc.y * inv, acc.z * inv, acc.w * inv);
        ((float4*)(out + (size_t)w * DIM))[sl] = v;
    }

    uint32_t h0 = f2h2(v.x, v.y), h1 = f2h2(v.z, v.w);
    *(uint2*)((char*)g_kvhi + ((size_t)w * DIM + sl * 4) * 2) = make_uint2(h0, h1);
}

// ---------------------------------------------------------------------------
// Entity aggregation: 64 rows/CTA (relS loaded once per 64 rows -> 1/4 of the
// per-block L2 table traffic). fp32 gathers (fp16 scores proven fatal in R15).
// ---------------------------------------------------------------------------
#define ENT_RPB 64
__global__ void __launch_bounds__(256, 4) ent_agg_kernel(
    const float* __restrict__ ent,
    const float* __restrict__ rel,
    const int*   __restrict__ nbe,
    const int*   __restrict__ nbr,
    float* __restrict__ out)
{
    __shared__ float relS[N_RELS * DIM];
    __shared__ int   eS[ENT_RPB * KNB];
    __shared__ int   rS[ENT_RPB * KNB];

    const int tid = threadIdx.x;
    for (int i = tid; i < N_RELS * DIM / 4; i += 256)
        ((float4*)relS)[i] = ((const float4*)rel)[i];
    const int rowbase = blockIdx.x * ENT_RPB;
    for (int i = tid; i < ENT_RPB * KNB; i += 256) {
        int rr = rowbase + i / KNB;
        bool ok = rr < N_ENT;
        eS[i] = ok ? __ldg(nbe + (size_t)rr * KNB + i % KNB) : 0;
        rS[i] = ok ? __ldg(nbr + (size_t)rr * KNB + i % KNB) : 0;
    }
    __syncthreads();

    const int wrp  = tid >> 5;
    const int lane = tid & 31;
    const int sl   = lane & 15;

    #pragma unroll 1
    for (int grp = 0; grp < ENT_RPB / 16; grp++) {
        const int rloc = grp * 16 + wrp * 2 + (lane >> 4);
        const int w    = rowbase + rloc;
        if (w >= N_ENT) continue;

        const float4 h = ((const float4*)(ent + (size_t)w * DIM))[sl];
        const int* re = eS + rloc * KNB;
        const int* rr = rS + rloc * KNB;

        float4 sx = make_float4(0.f, 0.f, 0.f, 0.f);
        #pragma unroll 4
        for (int k = 0; k < KNB; k++) {
            float4 a = ((const float4*)(relS + rr[k] * DIM))[sl];
            sx.x += a.x * a.x; sx.y += a.y * a.y;
            sx.z += a.z * a.z; sx.w += a.w * a.w;
        }
        float4 hn = make_float4(fabsf(h.x) * sqrtf(sx.x), fabsf(h.y) * sqrtf(sx.y),
                                fabsf(h.z) * sqrtf(sx.z), fabsf(h.w) * sqrtf(sx.w));

        float m = -CUDART_INF_F, l = 0.f;
        float4 acc = make_float4(0.f, 0.f, 0.f, 0.f);

        #pragma unroll 1
        for (int c0 = 0; c0 < KNB; c0 += 4) {
            float4 t[4];
            float  p[4];
            #pragma unroll
            for (int i = 0; i < 4; i++) {
                float4 ra = ((const float4*)(relS + rr[c0 + i] * DIM))[sl];
                t[i] = ((const float4*)(ent + (size_t)re[c0 + i] * DIM))[sl];
                p[i] = t[i].x * ra.x * hn.x + t[i].y * ra.y * hn.y
                     + t[i].z * ra.z * hn.z + t[i].w * ra.w * hn.w;
            }
            #pragma unroll
            for (int i = 0; i < 4; i++) {
                p[i] += __shfl_xor_sync(0xffffffffu, p[i], 1);
                p[i] += __shfl_xor_sync(0xffffffffu, p[i], 2);
                p[i] += __shfl_xor_sync(0xffffffffu, p[i], 4);
                p[i] += __shfl_xor_sync(0xffffffffu, p[i], 8);
                p[i] *= p[i];
            }
            float mx = fmaxf(fmaxf(p[0], p[1]), fmaxf(p[2], p[3]));
            if (mx > m) {
                float sc = __expf(m - mx);
                l *= sc;
                acc.x *= sc; acc.y *= sc; acc.z *= sc; acc.w *= sc;
                m = mx;
            }
            #pragma unroll
            for (int i = 0; i < 4; i++) {
                float e = __expf(p[i] - m);
                l += e;
                acc.x += e * t[i].x; acc.y += e * t[i].y;
                acc.z += e * t[i].z; acc.w += e * t[i].w;
            }
        }
        float inv = 1.f / l;
        ((float4*)(out + (size_t)w * DIM))[sl] =
            make_float4(acc.x * inv, acc.y * inv, acc.z * inv, acc.w * inv);
    }
}

// ---------------------------------------------------------------------------
// CSR build + gather + combine (unchanged).
// ---------------------------------------------------------------------------
__global__ void __launch_bounds__(256) hist_kernel(const int* __restrict__ rows)
{
    int i = blockIdx.x * 256 + threadIdx.x;
    if (i < NNZ_CNT) atomicAdd(&g_cnt[__ldg(rows + i)], 1);
}

__global__ void __launch_bounds__(1024) scan_kernel()
{
    __shared__ int wsum[32];
    __shared__ int carry;
    const int tid = threadIdx.x, lane = tid & 31, wid = tid >> 5;
    if (tid == 0) { carry = 0; g_off[0] = 0; }
    __syncthreads();
    for (int base = 0; base < N_USERS; base += 1024) {
        int i = base + tid;
        int v = (i < N_USERS) ? g_cnt[i] : 0;
        #pragma unroll
        for (int d = 1; d < 32; d <<= 1) {
            int y = __shfl_up_sync(0xffffffffu, v, d);
            if (lane >= d) v += y;
        }
        if (lane == 31) wsum[wid] = v;
        __syncthreads();
        if (wid == 0) {
            int w = wsum[lane];
            #pragma unroll
            for (int d = 1; d < 32; d <<= 1) {
                int y = __shfl_up_sync(0xffffffffu, w, d);
                if (lane >= d) w += y;
            }
            wsum[lane] = w;
        }
        __syncthreads();
        int incl = v + (wid ? wsum[wid - 1] : 0) + carry;
        if (i < N_USERS) g_off[i + 1] = incl;
        __syncthreads();
        if (tid == 1023) carry = incl;
        __syncthreads();
    }
}

__global__ void __launch_bounds__(256) scatter_kernel(
    const int* __restrict__ rows,
    const int* __restrict__ cols,
    const float* __restrict__ vals)
{
    int i = blockIdx.x * 256 + threadIdx.x;
    if (i >= NNZ_CNT) return;
    int r = __ldg(rows + i);
    int pos = g_off[r] + atomicAdd(&g_cnt[r], 1);
    g_pcv[pos] = make_int2(__ldg(cols + i), __float_as_int(__ldg(vals + i)));
}

__global__ void __launch_bounds__(256) gather_kernel(
    const float* __restrict__ news_agg,
    float* __restrict__ user_seg)
{
    int w    = (blockIdx.x * 256 + threadIdx.x) >> 5;
    int lane = threadIdx.x & 31;
    if (w >= N_USERS) return;
    int j = g_off[w], e = g_off[w + 1];
    float2 acc = make_float2(0.f, 0.f);
    for (; j + 4 <= e; j += 4) {
        int2 c0 = g_pcv[j], c1 = g_pcv[j+1], c2 = g_pcv[j+2], c3 = g_pcv[j+3];
        float2 a = *(const float2*)(news_agg + (size_t)c0.x * DIM + 2 * lane);
        float2 b = *(const float2*)(news_agg + (size_t)c1.x * DIM + 2 * lane);
        float2 c = *(const float2*)(news_agg + (size_t)c2.x * DIM + 2 * lane);
        float2 d = *(const float2*)(news_agg + (size_t)c3.x * DIM + 2 * lane);
        float v0 = __int_as_float(c0.y), v1 = __int_as_float(c1.y);
        float v2 = __int_as_float(c2.y), v3 = __int_as_float(c3.y);
        acc.x += v0*a.x + v1*b.x + v2*c.x + v3*d.x;
        acc.y += v0*a.y + v1*b.y + v2*c.y + v3*d.y;
    }
    for (; j < e; j++) {
        int2 cv = g_pcv[j];
        float2 a = *(const float2*)(news_agg + (size_t)cv.x * DIM + 2 * lane);
        float v = __int_as_float(cv.y);
        acc.x += v * a.x;
        acc.y += v * a.y;
    }
    *(float2*)(user_seg + (size_t)w * DIM + 2 * lane) = acc;
}

__global__ void __launch_bounds__(256) combine_kernel(float* __restrict__ user_out)
{
    int w    = (blockIdx.x * blockDim.x + threadIdx.x) >> 5;
    int lane = threadIdx.x & 31;
    if (w >= N_USERS) return;
    int qt = w >> 7, r = w & 127;

    float M = -CUDART_INF_F;
    float ms[KSPL], ls[KSPL];
    #pragma unroll
    for (int s = 0; s < KSPL; s++) {
        size_t u = (size_t)(qt * KSPL + s);
        ms[s] = g_pm[u * 128 + r];
        ls[s] = g_pl[u * 128 + r];
        M = fmaxf(M, ms[s]);
    }
    float L = 0.f, ax = 0.f, ay = 0.f;
    #pragma unroll
    for (int s = 0; s < KSPL; s++) {
        size_t u = (size_t)(qt * KSPL + s);
        float e = exp2f(ms[s] - M);
        L += e * ls[s];
        float2 o2 = ((const float2*)(g_po + (u * 128 + r) * 64))[lane];
        ax += e * o2.x;
        ay += e * o2.y;
    }
    float inv = 1.f / L;
    float2* up = (float2*)(user_out + (size_t)w * DIM);
    float2 sg = up[lane];
    up[lane] = make_float2(sg.x + ax * inv * sg.x,
                           sg.y + ay * inv * sg.y);
}

// ---------------------------------------------------------------------------
// Launch: 3-stream fork (R14 topology).
// ---------------------------------------------------------------------------
extern "C" void kernel_launch(void* const* d_in, const int* in_sizes, int n_in,
                              void* d_out, int out_size)
{
    const float* user_emb = (const float*)d_in[0];
    const float* news_emb = (const float*)d_in[1];
    const float* ent_emb  = (const float*)d_in[2];
    const float* rel_emb  = (const float*)d_in[3];
    const int*   news_ent = (const int*)d_in[4];
    const int*   news_rel = (const int*)d_in[5];
    const int*   nb_ent   = (const int*)d_in[6];
    const int*   nb_rel   = (const int*)d_in[7];
    const int*   irows    = (const int*)d_in[8];
    const int*   icols    = (const int*)d_in[9];
    const float* ivals    = (const float*)d_in[10];

    float* out      = (float*)d_out;
    float* news_out = out;
    float* ent_out  = out + (size_t)N_NEWS * DIM;
    float* user_out = ent_out + (size_t)N_ENT * DIM;

    static cudaStream_t s0 = nullptr, s1 = nullptr, s2 = nullptr;
    static cudaEvent_t  ev0, evNews, evG, evE, evDone;
    if (!s0) {
        int lo, hi;
        cudaDeviceGetStreamPriorityRange(&lo, &hi);
        cudaStreamCreateWithPriority(&s0, cudaStreamNonBlocking, hi);
        cudaStreamCreateWithPriority(&s1, cudaStreamNonBlocking, lo);
        cudaStreamCreateWithPriority(&s2, cudaStreamNonBlocking, hi);
        cudaEventCreateWithFlags(&ev0,    cudaEventDisableTiming);
        cudaEventCreateWithFlags(&evNews, cudaEventDisableTiming);
        cudaEventCreateWithFlags(&evG,    cudaEventDisableTiming);
        cudaEventCreateWithFlags(&evE,    cudaEventDisableTiming);
        cudaEventCreateWithFlags(&evDone, cudaEventDisableTiming);
        cudaFuncSetAttribute(attn_mma_kernel,
                             cudaFuncAttributeMaxDynamicSharedMemorySize, SMEM_ATT);
    }

    void* cnt_ptr = nullptr;
    cudaGetSymbolAddress(&cnt_ptr, g_cnt);

    cudaEventRecord(ev0, 0);
    cudaStreamWaitEvent(s0, ev0, 0);
    cudaStreamWaitEvent(s1, ev0, 0);
    cudaStreamWaitEvent(s2, ev0, 0);

    // s0 (high prio): news agg -> attn
    news_agg_kernel<<<(KVROWS + 15) / 16, 256, 0, s0>>>(
        news_emb, ent_emb, rel_emb, news_ent, news_rel, news_out);
    cudaEventRecord(evNews, s0);
    attn_mma_kernel<<<ATT_UNITS, 256, SMEM_ATT, s0>>>(user_emb);

    // s2 (equal prio): entity agg (fp32 gathers, 64 rows/CTA)
    ent_agg_kernel<<<(N_ENT + ENT_RPB - 1) / ENT_RPB, 256, 0, s2>>>(
        ent_emb, rel_emb, nb_ent, nb_rel, ent_out);
    cudaEventRecord(evE, s2);

    // s1 (low prio): CSR build, then gather after news agg
    cudaMemsetAsync(cnt_ptr, 0, N_USERS * sizeof(int), s1);
    hist_kernel<<<(NNZ_CNT + 255) / 256, 256, 0, s1>>>(irows);
    scan_kernel<<<1, 1024, 0, s1>>>();
    cudaMemsetAsync(cnt_ptr, 0, N_USERS * sizeof(int), s1);
    scatter_kernel<<<(NNZ_CNT + 255) / 256, 256, 0, s1>>>(irows, icols, ivals);
    cudaStreamWaitEvent(s1, evNews, 0);
    gather_kernel<<<(N_USERS * 32 + 255) / 256, 256, 0, s1>>>(news_out, user_out);
    cudaEventRecord(evG, s1);

    // s0: join gather, run combine
    cudaStreamWaitEvent(s0, evG, 0);
    combine_kernel<<<(N_USERS + 7) / 8, 256, 0, s0>>>(user_out);
    cudaEventRecord(evDone, s0);

    cudaStreamWaitEvent(0, evDone, 0);
    cudaStreamWaitEvent(0, evE, 0);
}